// round 10
// baseline (speedup 1.0000x reference)
#include <cuda_runtime.h>
#include <cstdint>
#include <math.h>

#define NEG_INF (__int_as_float(0xff800000))

// ---------------- problem constants ----------------
#define BATCH   16
#define NFEAT   16
#define TLEN    64
#define SCL     32
#define HID     128
#define FS      4
#define NHEAD   2
#define DHEAD   64

#define H1H     61
#define H1W     29
#define H2H     58
#define H2W     26
#define LSEQ    1508
#define UTOP    40

#define K1      256
#define K2      2048
#define M1      (BATCH*H1H*H1W)   // 28304
#define M2      (BATCH*LSEQ)      // 24128
#define BHCNT   (BATCH*NHEAD)     // 32

#define NSLICE  8
#define SLICE_LEN 189             // ceil(1508/8)

#if defined(__CUDA_ARCH_FEAT_SM103_ALL) || defined(__CUDA_ARCH_SPECIFIC__)
#define TC_PATH 1
#else
#define TC_PATH 0
#endif

// ---------------- scratch ----------------
__device__ float g_xcl[BATCH*TLEN*SCL*NFEAT];
__device__ float g_h1cl[M1*HID];
__device__ float g_seq[M2*HID];
__device__ float g_Q[BHCNT*LSEQ*DHEAD];
__device__ float g_K[BHCNT*LSEQ*DHEAD];
__device__ float g_V[BHCNT*LSEQ*DHEAD];
__device__ float g_M[BHCNT*LSEQ];
__device__ int   g_Mtop[BHCNT*UTOP];
__device__ float g_upd[BHCNT*UTOP*DHEAD];
__device__ float g_vmean[BHCNT*DHEAD];
__device__ float g_B1[HID*K1];
__device__ float g_B2[HID*K2];
__device__ float g_wqkvT[3*HID*HID];
__device__ float g_woT[HID*HID];
__device__ float g_pm[BHCNT*UTOP*NSLICE];
__device__ float g_ps[BHCNT*UTOP*NSLICE];
__device__ float g_pacc[BHCNT*UTOP*NSLICE*DHEAD];
__device__ int   g_sel[BHCNT*LSEQ];
__device__ float g_baseout[BATCH*HID];

// ---------------- PTX helpers ----------------
__device__ __forceinline__ uint32_t smem_u32(const void* p) {
    uint32_t a;
    asm("{ .reg .u64 t; cvta.to.shared.u64 t, %1; cvt.u32.u64 %0, t; }" : "=r"(a) : "l"(p));
    return a;
}

#define TC_ALLOC(sa, n) \
    asm volatile("tcgen05.alloc.cta_group::1.sync.aligned.shared::cta.b32 [%0], %1;" \
                 :: "r"(sa), "r"(n) : "memory")
#define TC_DEALLOC(t, n) \
    asm volatile("tcgen05.dealloc.cta_group::1.sync.aligned.b32 %0, %1;" :: "r"(t), "r"(n))
#define TC_RELINQ() \
    asm volatile("tcgen05.relinquish_alloc_permit.cta_group::1.sync.aligned;")
#define TC_COMMIT(mb) \
    asm volatile("tcgen05.commit.cta_group::1.mbarrier::arrive::one.shared::cluster.b64 [%0];" \
                 :: "r"(mb) : "memory")
#define TC_FENCE_AFTER()  asm volatile("tcgen05.fence::after_thread_sync;" ::: "memory")
#define TC_FENCE_BEFORE() asm volatile("tcgen05.fence::before_thread_sync;" ::: "memory")
#define TC_WAIT_LD()      asm volatile("tcgen05.wait::ld.sync.aligned;" ::: "memory")
#define MB_INIT(mb, c) \
    asm volatile("mbarrier.init.shared.b64 [%0], %1;" :: "r"(mb), "r"(c) : "memory")
#define FENCE_ASYNC() asm volatile("fence.proxy.async.shared::cta;" ::: "memory")

#define MB_WAIT_PARITY(mbar_smem_addr, phase_parity) do { \
    uint32_t _mbar = (uint32_t)(mbar_smem_addr); \
    uint32_t _parity = (uint32_t)(phase_parity); \
    uint32_t _done; \
    asm volatile( \
        "{\n\t" \
        ".reg .pred p;\n\t" \
        "mbarrier.try_wait.parity.acquire.cta.shared::cta.b64 p, [%1], %2;\n\t" \
        "selp.b32 %0, 1, 0, p;\n\t" \
        "}" \
        : "=r"(_done) : "r"(_mbar), "r"(_parity) : "memory"); \
    if (!_done) { \
        asm volatile( \
            "{\n\t" \
            ".reg .pred P1;\n\t" \
            "WAIT_LOOP_%=:\n\t" \
            "mbarrier.try_wait.parity.acquire.cta.shared::cta.b64 P1, [%0], %1, 0x989680;\n\t" \
            "@P1 bra.uni WAIT_DONE_%=;\n\t" \
            "bra.uni WAIT_LOOP_%=;\n\t" \
            "WAIT_DONE_%=:\n\t" \
            "}" \
            :: "r"(_mbar), "r"(_parity) : "memory"); \
    } \
} while(0)

#define TC_LD_X32(r, tmem_addr) \
    asm volatile( \
        "tcgen05.ld.sync.aligned.32x32b.x32.b32 " \
        "{%0, %1, %2, %3, %4, %5, %6, %7, " \
        " %8, %9, %10, %11, %12, %13, %14, %15, " \
        " %16, %17, %18, %19, %20, %21, %22, %23, " \
        " %24, %25, %26, %27, %28, %29, %30, %31}, [%32];" \
        : "=r"((r)[0]),  "=r"((r)[1]),  "=r"((r)[2]),  "=r"((r)[3]), \
          "=r"((r)[4]),  "=r"((r)[5]),  "=r"((r)[6]),  "=r"((r)[7]), \
          "=r"((r)[8]),  "=r"((r)[9]),  "=r"((r)[10]), "=r"((r)[11]), \
          "=r"((r)[12]), "=r"((r)[13]), "=r"((r)[14]), "=r"((r)[15]), \
          "=r"((r)[16]), "=r"((r)[17]), "=r"((r)[18]), "=r"((r)[19]), \
          "=r"((r)[20]), "=r"((r)[21]), "=r"((r)[22]), "=r"((r)[23]), \
          "=r"((r)[24]), "=r"((r)[25]), "=r"((r)[26]), "=r"((r)[27]), \
          "=r"((r)[28]), "=r"((r)[29]), "=r"((r)[30]), "=r"((r)[31]) \
        : "r"(tmem_addr))

#if TC_PATH
__device__ __forceinline__ void mma_tf32_ss(uint32_t d_tmem, uint64_t a_desc,
                                            uint64_t b_desc, uint32_t idesc, bool accum) {
    uint32_t en = accum ? 1u : 0u;
    asm volatile(
        "{\n\t"
        ".reg .pred p;\n\t"
        "setp.ne.u32 p, %4, 0;\n\t"
        "tcgen05.mma.cta_group::1.kind::tf32 [%0], %1, %2, %3, p;\n\t"
        "}"
        :: "r"(d_tmem), "l"(a_desc), "l"(b_desc), "r"(idesc), "r"(en)
        : "memory");
}
#endif

// SW128 SMEM descriptor: layout=2, version=1, SBO=64, LBO=1
__device__ __forceinline__ uint64_t make_desc(uint32_t addr) {
    return ((uint64_t)2 << 61) | ((uint64_t)1 << 46) | ((uint64_t)64 << 32)
         | ((uint64_t)1 << 16) | (uint64_t)((addr >> 4) & 0x3FFF);
}

__device__ __forceinline__ uint32_t swz128(uint32_t off) {
    return off ^ ((off >> 3) & 0x70);
}

__device__ __forceinline__ void split_tf32(float v, float& hi, float& lo) {
    uint32_t h;
    asm("cvt.rna.tf32.f32 %0, %1;" : "=r"(h) : "f"(v));
    hi = __uint_as_float(h);
    lo = v - hi;
}

// idesc: c=F32(1@4), a=TF32(2@7), b=TF32(2@10), N=128(16@17), M=128(8@24)
#define TF32_IDESC ((1u << 4) | (2u << 7) | (2u << 10) | (16u << 17) | (8u << 24))

// ---------------- fused prep kernel ----------------
#define PREP_S0 (BATCH*NFEAT*TLEN*SCL)
#define PREP_S1 (PREP_S0 + HID*K1)
#define PREP_S2 (PREP_S1 + HID*K2)
#define PREP_S3 (PREP_S2 + 3*HID*HID)
#define PREP_S4 (PREP_S3 + HID*HID)
__global__ void prep_kernel(const float* __restrict__ x,
                            const float* __restrict__ c1w, const float* __restrict__ c2w,
                            const float* __restrict__ wq, const float* __restrict__ wk,
                            const float* __restrict__ wv, const float* __restrict__ wo,
                            float* __restrict__ xcl, float* __restrict__ B1,
                            float* __restrict__ B2, float* __restrict__ wqkvT,
                            float* __restrict__ woT) {
    int idx = blockIdx.x * blockDim.x + threadIdx.x;
    if (idx < PREP_S0) {
        int w = idx % SCL;
        int h = (idx / SCL) % TLEN;
        int c = (idx / (SCL * TLEN)) % NFEAT;
        int b = idx / (SCL * TLEN * NFEAT);
        xcl[((b * TLEN + h) * SCL + w) * NFEAT + c] = x[idx];
    } else if (idx < PREP_S1) {
        int i = idx - PREP_S0;
        int n = i / K1, k = i % K1;
        int ic = k / 16, s = k % 16;
        B1[n * K1 + s * NFEAT + ic] = c1w[i];
    } else if (idx < PREP_S2) {
        int i = idx - PREP_S1;
        int n = i / K2, k = i % K2;
        int ic = k / 16, s = k % 16;
        B2[n * K2 + s * HID + ic] = c2w[i];
    } else if (idx < PREP_S3) {
        int i = idx - PREP_S2;
        int mat = i / (HID * HID);
        int r = i % (HID * HID);
        int a = r / HID, b = r % HID;
        const float* w = (mat == 0) ? wq : (mat == 1) ? wk : wv;
        wqkvT[mat * HID * HID + b * HID + a] = w[r];
    } else if (idx < PREP_S4) {
        int i = idx - PREP_S3;
        int a = i / HID, b = i % HID;
        woT[b * HID + a] = wo[i];
    }
}

// ---------------- tcgen05 3xTF32 GEMM (R8 config: BK=32, single buf, 2 CTA/SM) ---
#define GEMM_SMEM_BYTES (79872)

template<int MODE, int KDIM, bool RELU, int NMAT, int LAYOUT>
__global__ void __launch_bounds__(256, 2)
gemm_tc_kernel(const float* __restrict__ Ain, const float* __restrict__ BwAll,
               const float* __restrict__ b0, const float* __restrict__ b1p,
               const float* __restrict__ b2p,
               float* __restrict__ o0, float* __restrict__ o1p, float* __restrict__ o2p,
               int M) {
    const int mat = (NMAT > 1) ? blockIdx.y : 0;
    const float* Bw = BwAll + (size_t)mat * HID * KDIM;
    const float* bias = (mat == 0) ? b0 : (mat == 1) ? b1p : b2p;
    float* out = (mat == 0) ? o0 : (mat == 1) ? o1p : o2p;

#if TC_PATH
    extern __shared__ char dynraw[];
    __shared__ uint32_t s_tmem[1];
    __shared__ __align__(8) unsigned long long s_mbar[1];

    const int tid = threadIdx.x;
    const int wid = tid >> 5;
    const int lane = tid & 31;
    const int block_m = blockIdx.x * 128;

    uint32_t dynb32 = smem_u32(dynraw);
    uint32_t smem_base = (dynb32 + 1023u) & ~1023u;
    char* dbase = dynraw + (smem_base - dynb32);
    uint32_t mbar0 = smem_u32(&s_mbar[0]);

    if (wid == 0) {
        TC_ALLOC(smem_u32(s_tmem), 256);
        TC_RELINQ();               // free the per-SM alloc permit immediately
    }
    if (tid == 0) MB_INIT(mbar0, 1);
    __syncthreads();
    uint32_t tmem;
    asm volatile("ld.shared.b32 %0, [%1];" : "=r"(tmem) : "r"(smem_u32(s_tmem)));

    const int quad = tid & 7;
    int rowi[4], abase[4];
    bool aok[4];
#pragma unroll
    for (int i = 0; i < 4; i++) {
        rowi[i] = i * 32 + (tid >> 3);
        int m = block_m + rowi[i];
        aok[i] = (m < M);
        int mc = aok[i] ? m : 0;
        if (MODE == 0) {
            abase[i] = mc * KDIM;
        } else if (MODE == 1) {
            int b = mc / (H1H * H1W);
            int r = mc % (H1H * H1W);
            abase[i] = ((b * TLEN + r / H1W) * SCL + (r % H1W)) * NFEAT;
        } else {
            int b = mc / LSEQ;
            int r = mc % LSEQ;
            abase[i] = ((b * H1H + r / H2W) * H1W + (r % H2W)) * HID;
        }
    }
    uint32_t swz[4];
#pragma unroll
    for (int i = 0; i < 4; i++)
        swz[i] = swz128((uint32_t)rowi[i] * 128u + (uint32_t)quad * 16u);

    float4 areg[4], breg[4];
    auto load_regs = [&](int c) {
        const int kq = c * 32 + quad * 4;
#pragma unroll
        for (int i = 0; i < 4; i++) {
            areg[i] = make_float4(0.f, 0.f, 0.f, 0.f);
            if (aok[i]) {
                int addr;
                if (MODE == 0) {
                    addr = abase[i] + kq;
                } else if (MODE == 1) {
                    int s = kq >> 4, ic = kq & 15;
                    addr = abase[i] + (((s >> 2) * SCL) + (s & 3)) * NFEAT + ic;
                } else {
                    int s = kq >> 7, ic = kq & 127;
                    addr = abase[i] + (((s >> 2) * H1W) + (s & 3)) * HID + ic;
                }
                areg[i] = *reinterpret_cast<const float4*>(Ain + addr);
            }
            breg[i] = *reinterpret_cast<const float4*>(Bw + rowi[i] * KDIM + kq);
        }
    };
    auto store_tiles = [&]() {
        char* Ahi = dbase;
        char* Alo = Ahi + 16384;
        char* Bhi = Ahi + 32768;
        char* Blo = Ahi + 49152;
#pragma unroll
        for (int i = 0; i < 4; i++) {
            float4 h4, l4;
            split_tf32(areg[i].x, h4.x, l4.x);
            split_tf32(areg[i].y, h4.y, l4.y);
            split_tf32(areg[i].z, h4.z, l4.z);
            split_tf32(areg[i].w, h4.w, l4.w);
            *reinterpret_cast<float4*>(Ahi + swz[i]) = h4;
            *reinterpret_cast<float4*>(Alo + swz[i]) = l4;
            split_tf32(breg[i].x, h4.x, l4.x);
            split_tf32(breg[i].y, h4.y, l4.y);
            split_tf32(breg[i].z, h4.z, l4.z);
            split_tf32(breg[i].w, h4.w, l4.w);
            *reinterpret_cast<float4*>(Bhi + swz[i]) = h4;
            *reinterpret_cast<float4*>(Blo + swz[i]) = l4;
        }
    };

    const int NC = KDIM / 32;
    int ph = 0;
    load_regs(0);

    for (int c = 0; c < NC; c++) {
        if (c > 0) {
            MB_WAIT_PARITY(mbar0, ph);
            ph ^= 1;
        }
        store_tiles();
        if (c + 1 < NC) load_regs(c + 1);
        FENCE_ASYNC();
        __syncthreads();
        if (tid == 0) {
            uint64_t dah = make_desc(smem_base);
            uint64_t dal = make_desc(smem_base + 16384);
            uint64_t dbh = make_desc(smem_base + 32768);
            uint64_t dbl = make_desc(smem_base + 49152);
#pragma unroll
            for (int s = 0; s < 4; s++) {
                uint64_t o = (uint64_t)(s * 2);
                mma_tf32_ss(tmem, dah + o, dbh + o, TF32_IDESC, !(c == 0 && s == 0));
                mma_tf32_ss(tmem, dah + o, dbl + o, TF32_IDESC, true);
                mma_tf32_ss(tmem, dal + o, dbh + o, TF32_IDESC, true);
            }
            TC_COMMIT(mbar0);
        }
    }
    MB_WAIT_PARITY(mbar0, ph);
    TC_FENCE_AFTER();
    __syncthreads();

    if (wid < 4) {
        int m = block_m + wid * 32 + lane;
#pragma unroll
        for (int cb = 0; cb < 128; cb += 32) {
            uint32_t r[32];
            TC_LD_X32(r, tmem + cb);
            TC_WAIT_LD();
            if (m < M) {
                float vals[32];
#pragma unroll
                for (int j = 0; j < 32; j++) {
                    float v = __uint_as_float(r[j]) + __ldg(&bias[cb + j]);
                    if (RELU) v = fmaxf(v, 0.f);
                    vals[j] = v;
                }
                float* po;
                if (LAYOUT == 0) {
                    po = out + (size_t)m * HID + cb;
                } else {
                    int b = m / LSEQ, l = m % LSEQ;
                    int h = cb >> 6, d0 = cb & 63;
                    po = out + ((size_t)(b * NHEAD + h) * LSEQ + l) * DHEAD + d0;
                }
#pragma unroll
                for (int j = 0; j < 8; j++) {
                    *reinterpret_cast<float4*>(po + j * 4) =
                        make_float4(vals[j * 4], vals[j * 4 + 1], vals[j * 4 + 2], vals[j * 4 + 3]);
                }
            }
        }
        TC_FENCE_BEFORE();
    }
    __syncthreads();
    if (wid == 0) TC_DEALLOC(tmem, 256);
#else
    // naive fallback (family PTX pass; exact sm_103a cubin always preferred on GB300)
    const int tid = threadIdx.x;
    const int block_m = blockIdx.x * 128;
    for (int e = tid; e < 128 * 128; e += 256) {
        int mi = e >> 7, n = e & 127;
        int m = block_m + mi;
        if (m >= M) continue;
        float acc = 0.f;
        for (int k = 0; k < KDIM; k++) {
            float a;
            if (MODE == 0) {
                a = Ain[(size_t)m * KDIM + k];
            } else if (MODE == 1) {
                int b = m / (H1H * H1W), r = m % (H1H * H1W);
                int s = k >> 4, ic = k & 15;
                a = Ain[((b * TLEN + r / H1W + (s >> 2)) * SCL + (r % H1W) + (s & 3)) * NFEAT + ic];
            } else {
                int b = m / LSEQ, r = m % LSEQ;
                int s = k >> 7, ic = k & 127;
                a = Ain[((b * H1H + r / H2W + (s >> 2)) * H1W + (r % H2W) + (s & 3)) * HID + ic];
            }
            acc += a * Bw[n * KDIM + k];
        }
        acc += bias[n];
        if (RELU) acc = fmaxf(acc, 0.f);
        if (LAYOUT == 0) {
            out[(size_t)m * HID + n] = acc;
        } else {
            int b = m / LSEQ, l = m % LSEQ;
            int h = n >> 6, d = n & 63;
            out[((size_t)(b * NHEAD + h) * LSEQ + l) * DHEAD + d] = acc;
        }
    }
#endif
}

// ---------------- helpers ----------------
__device__ __forceinline__ float warp_sum(float v) {
    v += __shfl_xor_sync(0xffffffffu, v, 16);
    v += __shfl_xor_sync(0xffffffffu, v, 8);
    v += __shfl_xor_sync(0xffffffffu, v, 4);
    v += __shfl_xor_sync(0xffffffffu, v, 2);
    v += __shfl_xor_sync(0xffffffffu, v, 1);
    return v;
}

// ---------------- sampled scores -> M ----------------
__global__ void sampled_m_kernel(const float* __restrict__ Q, const float* __restrict__ K,
                                 const int* __restrict__ idxs, float* __restrict__ Mout) {
    int gwarp = (blockIdx.x * blockDim.x + threadIdx.x) >> 5;
    int lane = threadIdx.x & 31;
    if (gwarp >= BHCNT * LSEQ) return;
    int bh = gwarp / LSEQ;
    int l  = gwarp % LSEQ;
    const float* q = Q + (size_t)gwarp * DHEAD;
    float q0 = q[lane * 2], q1 = q[lane * 2 + 1];
    const float* Kb = K + (size_t)bh * LSEQ * DHEAD;
    float mx = NEG_INF, sm = 0.f;
#pragma unroll 1
    for (int u = 0; u < UTOP; u += 8) {
        float d[8];
#pragma unroll
        for (int j = 0; j < 8; j++) {
            int ki = __ldg(&idxs[l * UTOP + u + j]);
            const float* kr = Kb + (size_t)ki * DHEAD;
            d[j] = q0 * kr[lane * 2] + q1 * kr[lane * 2 + 1];
        }
#pragma unroll
        for (int j = 0; j < 8; j++) d[j] = warp_sum(d[j]);
#pragma unroll
        for (int j = 0; j < 8; j++) { mx = fmaxf(mx, d[j]); sm += d[j]; }
    }
    if (lane == 0) Mout[gwarp] = mx - sm / (float)LSEQ;
}

// ---------------- top-40 per (b,h) ----------------
__global__ void topk_kernel(const float* __restrict__ Min, int* __restrict__ Mtop) {
    __shared__ float vals[LSEQ];
    __shared__ float rv[256];
    __shared__ int   ri[256];
    int bh = blockIdx.x;
    int tid = threadIdx.x;
    for (int j = tid; j < LSEQ; j += 256) vals[j] = Min[bh * LSEQ + j];
    __syncthreads();
    for (int it = 0; it < UTOP; it++) {
        float best = NEG_INF;
        int bi = LSEQ;
        for (int j = tid; j < LSEQ; j += 256) {
            float v = vals[j];
            if (v > best) { best = v; bi = j; }
        }
        rv[tid] = best; ri[tid] = bi;
        __syncthreads();
        for (int s = 128; s > 0; s >>= 1) {
            if (tid < s) {
                float vo = rv[tid + s]; int io = ri[tid + s];
                if (vo > rv[tid] || (vo == rv[tid] && io < ri[tid])) { rv[tid] = vo; ri[tid] = io; }
            }
            __syncthreads();
        }
        if (tid == 0) {
            Mtop[bh * UTOP + it] = ri[0];
            vals[ri[0]] = NEG_INF;
        }
        __syncthreads();
    }
}

// ---------------- V mean per (b,h) ----------------
#define VSLICE 377    // LSEQ/4
__global__ void vmean_kernel(const float* __restrict__ V, float* __restrict__ vmean) {
    __shared__ float part[4][DHEAD];
    int bh = blockIdx.x;
    int tid = threadIdx.x;
    int d = tid & 63;
    int sl = tid >> 6;
    const float* Vb = V + (size_t)bh * LSEQ * DHEAD;
    float s = 0.f;
    int beg = sl * VSLICE, end = beg + VSLICE;
    for (int l = beg; l < end; l++) s += Vb[(size_t)l * DHEAD + d];
    part[sl][d] = s;
    __syncthreads();
    if (tid < DHEAD)
        vmean[bh * DHEAD + tid] =
            (part[0][tid] + part[1][tid] + part[2][tid] + part[3][tid]) / (float)LSEQ;
}

// ---------------- attention phase 1: (bh, slice) blocks, 40 shared queries ------
__global__ void __launch_bounds__(256)
attn_p1_kernel(const float* __restrict__ Q, const float* __restrict__ K,
               const float* __restrict__ V, const int* __restrict__ Mtop,
               float* __restrict__ pm, float* __restrict__ ps, float* __restrict__ pacc) {
    __shared__ float qs[UTOP][DHEAD];
    __shared__ int ls[UTOP];
    int slice = blockIdx.x % NSLICE;
    int bh = blockIdx.x / NSLICE;
    int tid = threadIdx.x;
    int wid = tid >> 5;
    int lane = tid & 31;

    if (tid < UTOP) ls[tid] = Mtop[bh * UTOP + tid];
    __syncthreads();
    for (int e = tid; e < UTOP * DHEAD; e += 256) {
        int u = e >> 6, d = e & 63;
        qs[u][d] = Q[((size_t)bh * LSEQ + ls[u]) * DHEAD + d];
    }
    __syncthreads();

    const float2* Kb = (const float2*)(K + (size_t)bh * LSEQ * DHEAD);
    const float2* Vb = (const float2*)(V + (size_t)bh * LSEQ * DHEAD);
    int beg = slice * SLICE_LEN;
    int end = beg + SLICE_LEN;
    if (end > LSEQ) end = LSEQ;

    const int u0 = wid * 5;   // 8 warps x 5 queries = 40
    float m[5], s[5], a0[5], a1[5];
#pragma unroll
    for (int j = 0; j < 5; j++) { m[j] = NEG_INF; s[j] = 0.f; a0[j] = 0.f; a1[j] = 0.f; }

    float2 q2[5];
#pragma unroll
    for (int j = 0; j < 5; j++)
        q2[j] = *reinterpret_cast<const float2*>(&qs[u0 + j][lane * 2]);

#pragma unroll 1
    for (int k = beg; k < end; k++) {
        float2 kk = Kb[(size_t)k * 32 + lane];
        float2 vv = Vb[(size_t)k * 32 + lane];
        float d[5];
#pragma unroll
        for (int j = 0; j < 5; j++)
            d[j] = q2[j].x * kk.x + q2[j].y * kk.y;
#pragma unroll
        for (int j = 0; j < 5; j++) d[j] = warp_sum(d[j]) * 0.125f;
#pragma unroll
        for (int j = 0; j < 5; j++) {
            float nm = fmaxf(m[j], d[j]);
            float c = __expf(m[j] - nm);
            float p = __expf(d[j] - nm);
            s[j] = s[j] * c + p;
            a0[j] = a0[j] * c + p * vv.x;
            a1[j] = a1[j] * c + p * vv.y;
            m[j] = nm;
        }
    }
#pragma unroll
    for (int j = 0; j < 5; j++) {
        int pidx = (bh * UTOP + u0 + j) * NSLICE + slice;
        if (lane == 0) { pm[pidx] = m[j]; ps[pidx] = s[j]; }
        pacc[(size_t)pidx * DHEAD + lane * 2]     = a0[j];
        pacc[(size_t)pidx * DHEAD + lane * 2 + 1] = a1[j];
    }
}

// ---------------- attention phase 2: merge 8 slice partials per query -----------
__global__ void attn_p2_kernel(const float* __restrict__ pm, const float* __restrict__ ps,
                               const float* __restrict__ pacc, float* __restrict__ upd) {
    int gw = (blockIdx.x * blockDim.x + threadIdx.x) >> 5;
    int lane = threadIdx.x & 31;
    if (gw >= BHCNT * UTOP) return;
    int base = gw * NSLICE;
    float M = NEG_INF;
#pragma unroll
    for (int i = 0; i < NSLICE; i++) M = fmaxf(M, pm[base + i]);
    float S = 0.f, acc0 = 0.f, acc1 = 0.f;
#pragma unroll
    for (int i = 0; i < NSLICE; i++) {
        float c = __expf(pm[base + i] - M);
        S += ps[base + i] * c;
        acc0 += pacc[(size_t)(base + i) * DHEAD + lane * 2] * c;
        acc1 += pacc[(size_t)(base + i) * DHEAD + lane * 2 + 1] * c;
    }
    float inv = 1.f / S;
    upd[(size_t)gw * DHEAD + lane * 2]     = acc0 * inv;
    upd[(size_t)gw * DHEAD + lane * 2 + 1] = acc1 * inv;
}

// ---------------- sel map ----------------
__global__ void selinit_kernel(int* __restrict__ sel) {
    int idx = blockIdx.x * blockDim.x + threadIdx.x;
    if (idx < BHCNT * LSEQ) sel[idx] = -1;
}
__global__ void selset_kernel(const int* __restrict__ Mtop, int* __restrict__ sel) {
    int idx = blockIdx.x * blockDim.x + threadIdx.x;
    if (idx >= BHCNT * UTOP) return;
    sel[(idx / UTOP) * LSEQ + Mtop[idx]] = idx % UTOP;
}

// ---------------- baseout: vmean-row @ wo + bo, per batch ----------------
__global__ void baseout_kernel(const float* __restrict__ vmean, const float* __restrict__ woT,
                               const float* __restrict__ bo, float* __restrict__ baseout) {
    __shared__ float vr[HID];
    int b = blockIdx.x;
    int n = threadIdx.x;  // 128
    vr[n] = vmean[b * HID + n];
    __syncthreads();
    float acc = bo[n];
    const float4* wrow = (const float4*)(woT + n * HID);
#pragma unroll
    for (int k4 = 0; k4 < 32; k4++) {
        float4 wv = wrow[k4];
        acc += vr[k4 * 4] * wv.x + vr[k4 * 4 + 1] * wv.y
             + vr[k4 * 4 + 2] * wv.z + vr[k4 * 4 + 3] * wv.w;
    }
    baseout[b * HID + n] = acc;
}

// ---------------- fill out with baseout ----------------
__global__ void fillout_kernel(const float* __restrict__ baseout, float* __restrict__ out) {
    int idx = blockIdx.x * blockDim.x + threadIdx.x;
    if (idx >= M2 * HID) return;
    int m = idx >> 7;
    int b = m / LSEQ;
    out[idx] = baseout[b * HID + (idx & 127)];
}

// ---------------- correction: recompute selected rows exactly ----------------
__global__ void __launch_bounds__(256)
correction_kernel(const int* __restrict__ Mtop, const int* __restrict__ sel,
                  const float* __restrict__ upd, const float* __restrict__ vmean,
                  const float* __restrict__ woT, const float* __restrict__ bo,
                  float* __restrict__ out) {
    __shared__ float rowv[8][HID];
    int wid = threadIdx.x >> 5;
    int lane = threadIdx.x & 31;
    int gw = blockIdx.x * 8 + wid;
    if (gw >= BHCNT * UTOP) return;
    int bh = gw / UTOP;
    int b = bh >> 1, h = bh & 1;
    int l = Mtop[gw];
    // if head 0 also selected this l, its entry covers the row; skip duplicate
    if (h == 1 && sel[(b * 2) * LSEQ + l] >= 0) return;
#pragma unroll
    for (int hh = 0; hh < 2; hh++) {
        int bhh = b * 2 + hh;
        int uu = sel[bhh * LSEQ + l];
        const float* src = (uu >= 0) ? (upd + ((size_t)bhh * UTOP + uu) * DHEAD)
                                     : (vmean + bhh * DHEAD);
        rowv[wid][hh * 64 + lane * 2]     = src[lane * 2];
        rowv[wid][hh * 64 + lane * 2 + 1] = src[lane * 2 + 1];
    }
    __syncwarp();
    float* orow = out + ((size_t)(b * LSEQ) + l) * HID;
#pragma unroll
    for (int jn = 0; jn < 4; jn++) {
        int n = lane * 4 + jn;
        float acc = bo[n];
        const float4* wrow = (const float4*)(woT + n * HID);
#pragma unroll
        for (int k4 = 0; k4 < 32; k4++) {
            float4 wv = wrow[k4];
            acc += rowv[wid][k4 * 4] * wv.x + rowv[wid][k4 * 4 + 1] * wv.y
                 + rowv[wid][k4 * 4 + 2] * wv.z + rowv[wid][k4 * 4 + 3] * wv.w;
        }
        orow[n] = acc;
    }
}

// ---------------- launch ----------------
extern "C" void kernel_launch(void* const* d_in, const int* in_sizes, int n_in,
                              void* d_out, int out_size) {
    const float* x       = (const float*)d_in[0];
    const float* conv1_w = (const float*)d_in[1];
    const float* conv1_b = (const float*)d_in[2];
    const float* conv2_w = (const float*)d_in[3];
    const float* conv2_b = (const float*)d_in[4];
    const float* wq = (const float*)d_in[5];
    const float* bq = (const float*)d_in[6];
    const float* wk = (const float*)d_in[7];
    const float* bk = (const float*)d_in[8];
    const float* wv = (const float*)d_in[9];
    const float* bv = (const float*)d_in[10];
    const float* wo = (const float*)d_in[11];
    const float* bo = (const float*)d_in[12];
    const int* index_sample = (const int*)d_in[13];
    float* out = (float*)d_out;

    float *xcl, *h1cl, *seq, *Qp, *Kp, *Vp, *Mv, *updv, *vmeanv;
    float *B1, *B2, *wqkvT, *woT, *pm, *ps, *pacc, *baseout;
    int *mtop, *sel;
    cudaGetSymbolAddress((void**)&xcl, g_xcl);
    cudaGetSymbolAddress((void**)&h1cl, g_h1cl);
    cudaGetSymbolAddress((void**)&seq, g_seq);
    cudaGetSymbolAddress((void**)&Qp, g_Q);
    cudaGetSymbolAddress((void**)&Kp, g_K);
    cudaGetSymbolAddress((void**)&Vp, g_V);
    cudaGetSymbolAddress((void**)&Mv, g_M);
    cudaGetSymbolAddress((void**)&mtop, g_Mtop);
    cudaGetSymbolAddress((void**)&updv, g_upd);
    cudaGetSymbolAddress((void**)&vmeanv, g_vmean);
    cudaGetSymbolAddress((void**)&B1, g_B1);
    cudaGetSymbolAddress((void**)&B2, g_B2);
    cudaGetSymbolAddress((void**)&wqkvT, g_wqkvT);
    cudaGetSymbolAddress((void**)&woT, g_woT);
    cudaGetSymbolAddress((void**)&pm, g_pm);
    cudaGetSymbolAddress((void**)&ps, g_ps);
    cudaGetSymbolAddress((void**)&pacc, g_pacc);
    cudaGetSymbolAddress((void**)&sel, g_sel);
    cudaGetSymbolAddress((void**)&baseout, g_baseout);

    cudaFuncSetAttribute((const void*)gemm_tc_kernel<1, K1, true, 1, 0>,
                         cudaFuncAttributeMaxDynamicSharedMemorySize, GEMM_SMEM_BYTES);
    cudaFuncSetAttribute((const void*)gemm_tc_kernel<2, K2, true, 1, 0>,
                         cudaFuncAttributeMaxDynamicSharedMemorySize, GEMM_SMEM_BYTES);
    cudaFuncSetAttribute((const void*)gemm_tc_kernel<0, HID, false, 3, 1>,
                         cudaFuncAttributeMaxDynamicSharedMemorySize, GEMM_SMEM_BYTES);

    // fused prep
    prep_kernel<<<(PREP_S4 + 255) / 256, 256>>>(x, conv1_w, conv2_w, wq, wk, wv, wo,
                                                xcl, B1, B2, wqkvT, woT);

    // conv1 -> h1cl, relu
    gemm_tc_kernel<1, K1, true, 1, 0>
        <<<(M1 + 127) / 128, 256, GEMM_SMEM_BYTES>>>(xcl, B1, conv1_b, conv1_b, conv1_b,
                                                     h1cl, h1cl, h1cl, M1);

    // conv2 -> seq, relu
    gemm_tc_kernel<2, K2, true, 1, 0>
        <<<(M2 + 127) / 128, 256, GEMM_SMEM_BYTES>>>(h1cl, B2, conv2_b, conv2_b, conv2_b,
                                                     seq, seq, seq, M2);

    // QKV: grid.y = 3, head layout
    gemm_tc_kernel<0, HID, false, 3, 1>
        <<<dim3((M2 + 127) / 128, 3), 256, GEMM_SMEM_BYTES>>>(seq, wqkvT, bq, bk, bv,
                                                              Qp, Kp, Vp, M2);

    // sampled scores -> M
    {
        int warps = BHCNT * LSEQ;
        sampled_m_kernel<<<(warps + 7) / 8, 256>>>(Qp, Kp, index_sample, Mv);
    }

    topk_kernel<<<BHCNT, 256>>>(Mv, mtop);
    vmean_kernel<<<BHCNT, 256>>>(Vp, vmeanv);

    // sel map
    selinit_kernel<<<(BHCNT * LSEQ + 255) / 256, 256>>>(sel);
    selset_kernel<<<(BHCNT * UTOP + 255) / 256, 256>>>(mtop, sel);

    // two-phase attention
    attn_p1_kernel<<<BHCNT * NSLICE, 256>>>(Qp, Kp, Vp, mtop, pm, ps, pacc);
    attn_p2_kernel<<<(BHCNT * UTOP * 32 + 255) / 256, 256>>>(pm, ps, pacc, updv);

    // output: baseout broadcast + selected-row correction
    baseout_kernel<<<BATCH, HID>>>(vmeanv, woT, bo, baseout);
    fillout_kernel<<<(M2 * HID + 255) / 256, 256>>>(baseout, out);
    correction_kernel<<<(BHCNT * UTOP + 7) / 8, 256>>>(mtop, sel, updv, vmeanv,
                                                       woT, bo, out);
}

// round 11
// speedup vs baseline: 1.0410x; 1.0410x over previous
#include <cuda_runtime.h>
#include <cstdint>
#include <math.h>

#define NEG_INF (__int_as_float(0xff800000))

// ---------------- problem constants ----------------
#define BATCH   16
#define NFEAT   16
#define TLEN    64
#define SCL     32
#define HID     128
#define FS      4
#define NHEAD   2
#define DHEAD   64

#define H1H     61
#define H1W     29
#define H2H     58
#define H2W     26
#define LSEQ    1508
#define UTOP    40

#define K1      256
#define K2      2048
#define M1      (BATCH*H1H*H1W)   // 28304
#define M2      (BATCH*LSEQ)      // 24128
#define BHCNT   (BATCH*NHEAD)     // 32

#if defined(__CUDA_ARCH_FEAT_SM103_ALL) || defined(__CUDA_ARCH_SPECIFIC__)
#define TC_PATH 1
#else
#define TC_PATH 0
#endif

// ---------------- scratch (hi/lo pre-split operands) ----------------
__device__ float g_xh[BATCH*TLEN*SCL*NFEAT];
__device__ float g_xl[BATCH*TLEN*SCL*NFEAT];
__device__ float g_h1h[M1*HID];
__device__ float g_h1l[M1*HID];
__device__ float g_seqh[M2*HID];
__device__ float g_seql[M2*HID];
__device__ float g_ctxh[M2*HID];
__device__ float g_ctxl[M2*HID];
__device__ float g_Q[BHCNT*LSEQ*DHEAD];
__device__ float g_K[BHCNT*LSEQ*DHEAD];
__device__ float g_V[BHCNT*LSEQ*DHEAD];
__device__ float g_M[BHCNT*LSEQ];
__device__ int   g_Mtop[BHCNT*UTOP];
__device__ float g_upd[BHCNT*UTOP*DHEAD];
__device__ float g_vmean[BHCNT*DHEAD];
__device__ float g_B1h[HID*K1];
__device__ float g_B1l[HID*K1];
__device__ float g_B2h[HID*K2];
__device__ float g_B2l[HID*K2];
__device__ float g_wqkvTh[3*HID*HID];
__device__ float g_wqkvTl[3*HID*HID];
__device__ float g_woTh[HID*HID];
__device__ float g_woTl[HID*HID];

// ---------------- PTX helpers ----------------
__device__ __forceinline__ uint32_t smem_u32(const void* p) {
    uint32_t a;
    asm("{ .reg .u64 t; cvta.to.shared.u64 t, %1; cvt.u32.u64 %0, t; }" : "=r"(a) : "l"(p));
    return a;
}

#define TC_ALLOC(sa, n) \
    asm volatile("tcgen05.alloc.cta_group::1.sync.aligned.shared::cta.b32 [%0], %1;" \
                 :: "r"(sa), "r"(n) : "memory")
#define TC_DEALLOC(t, n) \
    asm volatile("tcgen05.dealloc.cta_group::1.sync.aligned.b32 %0, %1;" :: "r"(t), "r"(n))
#define TC_RELINQ() \
    asm volatile("tcgen05.relinquish_alloc_permit.cta_group::1.sync.aligned;")
#define TC_COMMIT(mb) \
    asm volatile("tcgen05.commit.cta_group::1.mbarrier::arrive::one.shared::cluster.b64 [%0];" \
                 :: "r"(mb) : "memory")
#define TC_FENCE_AFTER()  asm volatile("tcgen05.fence::after_thread_sync;" ::: "memory")
#define TC_FENCE_BEFORE() asm volatile("tcgen05.fence::before_thread_sync;" ::: "memory")
#define TC_WAIT_LD()      asm volatile("tcgen05.wait::ld.sync.aligned;" ::: "memory")
#define MB_INIT(mb, c) \
    asm volatile("mbarrier.init.shared.b64 [%0], %1;" :: "r"(mb), "r"(c) : "memory")
#define FENCE_ASYNC() asm volatile("fence.proxy.async.shared::cta;" ::: "memory")

#define MB_WAIT_PARITY(mbar_smem_addr, phase_parity) do { \
    uint32_t _mbar = (uint32_t)(mbar_smem_addr); \
    uint32_t _parity = (uint32_t)(phase_parity); \
    uint32_t _done; \
    asm volatile( \
        "{\n\t" \
        ".reg .pred p;\n\t" \
        "mbarrier.try_wait.parity.acquire.cta.shared::cta.b64 p, [%1], %2;\n\t" \
        "selp.b32 %0, 1, 0, p;\n\t" \
        "}" \
        : "=r"(_done) : "r"(_mbar), "r"(_parity) : "memory"); \
    if (!_done) { \
        asm volatile( \
            "{\n\t" \
            ".reg .pred P1;\n\t" \
            "WAIT_LOOP_%=:\n\t" \
            "mbarrier.try_wait.parity.acquire.cta.shared::cta.b64 P1, [%0], %1, 0x989680;\n\t" \
            "@P1 bra.uni WAIT_DONE_%=;\n\t" \
            "bra.uni WAIT_LOOP_%=;\n\t" \
            "WAIT_DONE_%=:\n\t" \
            "}" \
            :: "r"(_mbar), "r"(_parity) : "memory"); \
    } \
} while(0)

#define TC_LD_X32(r, tmem_addr) \
    asm volatile( \
        "tcgen05.ld.sync.aligned.32x32b.x32.b32 " \
        "{%0, %1, %2, %3, %4, %5, %6, %7, " \
        " %8, %9, %10, %11, %12, %13, %14, %15, " \
        " %16, %17, %18, %19, %20, %21, %22, %23, " \
        " %24, %25, %26, %27, %28, %29, %30, %31}, [%32];" \
        : "=r"((r)[0]),  "=r"((r)[1]),  "=r"((r)[2]),  "=r"((r)[3]), \
          "=r"((r)[4]),  "=r"((r)[5]),  "=r"((r)[6]),  "=r"((r)[7]), \
          "=r"((r)[8]),  "=r"((r)[9]),  "=r"((r)[10]), "=r"((r)[11]), \
          "=r"((r)[12]), "=r"((r)[13]), "=r"((r)[14]), "=r"((r)[15]), \
          "=r"((r)[16]), "=r"((r)[17]), "=r"((r)[18]), "=r"((r)[19]), \
          "=r"((r)[20]), "=r"((r)[21]), "=r"((r)[22]), "=r"((r)[23]), \
          "=r"((r)[24]), "=r"((r)[25]), "=r"((r)[26]), "=r"((r)[27]), \
          "=r"((r)[28]), "=r"((r)[29]), "=r"((r)[30]), "=r"((r)[31]) \
        : "r"(tmem_addr))

#if TC_PATH
__device__ __forceinline__ void mma_tf32_ss(uint32_t d_tmem, uint64_t a_desc,
                                            uint64_t b_desc, uint32_t idesc, bool accum) {
    uint32_t en = accum ? 1u : 0u;
    asm volatile(
        "{\n\t"
        ".reg .pred p;\n\t"
        "setp.ne.u32 p, %4, 0;\n\t"
        "tcgen05.mma.cta_group::1.kind::tf32 [%0], %1, %2, %3, p;\n\t"
        "}"
        :: "r"(d_tmem), "l"(a_desc), "l"(b_desc), "r"(idesc), "r"(en)
        : "memory");
}
#endif

// SW128 SMEM descriptor: layout=2, version=1, SBO=64, LBO=1
__device__ __forceinline__ uint64_t make_desc(uint32_t addr) {
    return ((uint64_t)2 << 61) | ((uint64_t)1 << 46) | ((uint64_t)64 << 32)
         | ((uint64_t)1 << 16) | (uint64_t)((addr >> 4) & 0x3FFF);
}

__device__ __forceinline__ uint32_t swz128(uint32_t off) {
    return off ^ ((off >> 3) & 0x70);
}

__device__ __forceinline__ void split_tf32(float v, float& hi, float& lo) {
    uint32_t h;
    asm("cvt.rna.tf32.f32 %0, %1;" : "=r"(h) : "f"(v));
    hi = __uint_as_float(h);
    lo = v - hi;
}

// idesc: c=F32(1@4), a=TF32(2@7), b=TF32(2@10), N=128(16@17), M=128(8@24)
#define TF32_IDESC ((1u << 4) | (2u << 7) | (2u << 10) | (16u << 17) | (8u << 24))

// ---------------- fused prep kernel: remap + pre-split everything ----------------
#define PREP_S0 (BATCH*NFEAT*TLEN*SCL)
#define PREP_S1 (PREP_S0 + HID*K1)
#define PREP_S2 (PREP_S1 + HID*K2)
#define PREP_S3 (PREP_S2 + 3*HID*HID)
#define PREP_S4 (PREP_S3 + HID*HID)
__global__ void prep_kernel(const float* __restrict__ x,
                            const float* __restrict__ c1w, const float* __restrict__ c2w,
                            const float* __restrict__ wq, const float* __restrict__ wk,
                            const float* __restrict__ wv, const float* __restrict__ wo,
                            float* __restrict__ xh, float* __restrict__ xl,
                            float* __restrict__ B1h, float* __restrict__ B1l,
                            float* __restrict__ B2h, float* __restrict__ B2l,
                            float* __restrict__ wqkvTh, float* __restrict__ wqkvTl,
                            float* __restrict__ woTh, float* __restrict__ woTl) {
    int idx = blockIdx.x * blockDim.x + threadIdx.x;
    float v, hh, ll;
    if (idx < PREP_S0) {
        int w = idx % SCL;
        int h = (idx / SCL) % TLEN;
        int c = (idx / (SCL * TLEN)) % NFEAT;
        int b = idx / (SCL * TLEN * NFEAT);
        int o = ((b * TLEN + h) * SCL + w) * NFEAT + c;
        v = x[idx];
        split_tf32(v, hh, ll);
        xh[o] = hh; xl[o] = ll;
    } else if (idx < PREP_S1) {
        int i = idx - PREP_S0;
        int n = i / K1, k = i % K1;
        int ic = k / 16, s = k % 16;
        int o = n * K1 + s * NFEAT + ic;
        v = c1w[i];
        split_tf32(v, hh, ll);
        B1h[o] = hh; B1l[o] = ll;
    } else if (idx < PREP_S2) {
        int i = idx - PREP_S1;
        int n = i / K2, k = i % K2;
        int ic = k / 16, s = k % 16;
        int o = n * K2 + s * HID + ic;
        v = c2w[i];
        split_tf32(v, hh, ll);
        B2h[o] = hh; B2l[o] = ll;
    } else if (idx < PREP_S3) {
        int i = idx - PREP_S2;
        int mat = i / (HID * HID);
        int r = i % (HID * HID);
        int a = r / HID, b = r % HID;
        const float* w = (mat == 0) ? wq : (mat == 1) ? wk : wv;
        int o = mat * HID * HID + b * HID + a;
        v = w[r];
        split_tf32(v, hh, ll);
        wqkvTh[o] = hh; wqkvTl[o] = ll;
    } else if (idx < PREP_S4) {
        int i = idx - PREP_S3;
        int a = i / HID, b = i % HID;
        int o = b * HID + a;
        v = wo[i];
        split_tf32(v, hh, ll);
        woTh[o] = hh; woTl[o] = ll;
    }
}

// ---------------- tcgen05 3xTF32 GEMM (pre-split hi/lo inputs) ----------------
// R8 structure: BK=32, single 64K buffer (78K request -> 2 CTA/SM), reg prefetch,
// alloc permit relinquished immediately. Mainloop is pure LDG->STS (no cvt/sub).
// OSPLIT: epilogue writes hi/lo output pair (o0=hi, o1p=lo), LAYOUT 0.
#define GEMM_SMEM_BYTES (79872)

template<int MODE, int KDIM, bool RELU, int NMAT, int LAYOUT, bool OSPLIT>
__global__ void __launch_bounds__(256, 2)
gemm_tc_kernel(const float* __restrict__ Ah, const float* __restrict__ Al,
               const float* __restrict__ BhAll, const float* __restrict__ BlAll,
               const float* __restrict__ b0, const float* __restrict__ b1p,
               const float* __restrict__ b2p,
               float* __restrict__ o0, float* __restrict__ o1p, float* __restrict__ o2p,
               int M) {
    const int mat = (NMAT > 1) ? blockIdx.y : 0;
    const float* Bh = BhAll + (size_t)mat * HID * KDIM;
    const float* Bl = BlAll + (size_t)mat * HID * KDIM;
    const float* bias = (mat == 0) ? b0 : (mat == 1) ? b1p : b2p;

#if TC_PATH
    extern __shared__ char dynraw[];
    __shared__ uint32_t s_tmem[1];
    __shared__ __align__(8) unsigned long long s_mbar[1];

    const int tid = threadIdx.x;
    const int wid = tid >> 5;
    const int lane = tid & 31;
    const int block_m = blockIdx.x * 128;

    uint32_t dynb32 = smem_u32(dynraw);
    uint32_t smem_base = (dynb32 + 1023u) & ~1023u;
    char* dbase = dynraw + (smem_base - dynb32);
    uint32_t mbar0 = smem_u32(&s_mbar[0]);

    if (wid == 0) {
        TC_ALLOC(smem_u32(s_tmem), 256);
        TC_RELINQ();
    }
    if (tid == 0) MB_INIT(mbar0, 1);
    __syncthreads();
    uint32_t tmem;
    asm volatile("ld.shared.b32 %0, [%1];" : "=r"(tmem) : "r"(smem_u32(s_tmem)));

    const int quad = tid & 7;
    int rowi[4], abase[4];
    bool aok[4];
#pragma unroll
    for (int i = 0; i < 4; i++) {
        rowi[i] = i * 32 + (tid >> 3);
        int m = block_m + rowi[i];
        aok[i] = (m < M);
        int mc = aok[i] ? m : 0;
        if (MODE == 0) {
            abase[i] = mc * KDIM;
        } else if (MODE == 1) {
            int b = mc / (H1H * H1W);
            int r = mc % (H1H * H1W);
            abase[i] = ((b * TLEN + r / H1W) * SCL + (r % H1W)) * NFEAT;
        } else {
            int b = mc / LSEQ;
            int r = mc % LSEQ;
            abase[i] = ((b * H1H + r / H2W) * H1W + (r % H2W)) * HID;
        }
    }
    uint32_t swz[4];
#pragma unroll
    for (int i = 0; i < 4; i++)
        swz[i] = swz128((uint32_t)rowi[i] * 128u + (uint32_t)quad * 16u);

    float4 ah[4], al[4], bh[4], bl[4];
    auto load_regs = [&](int c) {
        const int kq = c * 32 + quad * 4;
#pragma unroll
        for (int i = 0; i < 4; i++) {
            ah[i] = make_float4(0.f, 0.f, 0.f, 0.f);
            al[i] = make_float4(0.f, 0.f, 0.f, 0.f);
            if (aok[i]) {
                int addr;
                if (MODE == 0) {
                    addr = abase[i] + kq;
                } else if (MODE == 1) {
                    int s = kq >> 4, ic = kq & 15;
                    addr = abase[i] + (((s >> 2) * SCL) + (s & 3)) * NFEAT + ic;
                } else {
                    int s = kq >> 7, ic = kq & 127;
                    addr = abase[i] + (((s >> 2) * H1W) + (s & 3)) * HID + ic;
                }
                ah[i] = *reinterpret_cast<const float4*>(Ah + addr);
                al[i] = *reinterpret_cast<const float4*>(Al + addr);
            }
            bh[i] = *reinterpret_cast<const float4*>(Bh + rowi[i] * KDIM + kq);
            bl[i] = *reinterpret_cast<const float4*>(Bl + rowi[i] * KDIM + kq);
        }
    };
    auto store_tiles = [&]() {
        char* Ahi = dbase;
        char* Alo = Ahi + 16384;
        char* Bhi = Ahi + 32768;
        char* Blo = Ahi + 49152;
#pragma unroll
        for (int i = 0; i < 4; i++) {
            *reinterpret_cast<float4*>(Ahi + swz[i]) = ah[i];
            *reinterpret_cast<float4*>(Alo + swz[i]) = al[i];
            *reinterpret_cast<float4*>(Bhi + swz[i]) = bh[i];
            *reinterpret_cast<float4*>(Blo + swz[i]) = bl[i];
        }
    };

    const int NC = KDIM / 32;
    int ph = 0;
    load_regs(0);

    for (int c = 0; c < NC; c++) {
        if (c > 0) {
            MB_WAIT_PARITY(mbar0, ph);
            ph ^= 1;
        }
        store_tiles();
        if (c + 1 < NC) load_regs(c + 1);
        FENCE_ASYNC();
        __syncthreads();
        if (tid == 0) {
            uint64_t dah = make_desc(smem_base);
            uint64_t dal = make_desc(smem_base + 16384);
            uint64_t dbh = make_desc(smem_base + 32768);
            uint64_t dbl = make_desc(smem_base + 49152);
#pragma unroll
            for (int s = 0; s < 4; s++) {
                uint64_t o = (uint64_t)(s * 2);
                mma_tf32_ss(tmem, dah + o, dbh + o, TF32_IDESC, !(c == 0 && s == 0));
                mma_tf32_ss(tmem, dah + o, dbl + o, TF32_IDESC, true);
                mma_tf32_ss(tmem, dal + o, dbh + o, TF32_IDESC, true);
            }
            TC_COMMIT(mbar0);
        }
    }
    MB_WAIT_PARITY(mbar0, ph);
    TC_FENCE_AFTER();
    __syncthreads();

    if (wid < 4) {
        int m = block_m + wid * 32 + lane;
#pragma unroll
        for (int cb = 0; cb < 128; cb += 32) {
            uint32_t r[32];
            TC_LD_X32(r, tmem + cb);
            TC_WAIT_LD();
            if (m < M) {
                float vals[32];
#pragma unroll
                for (int j = 0; j < 32; j++) {
                    float v = __uint_as_float(r[j]) + __ldg(&bias[cb + j]);
                    if (RELU) v = fmaxf(v, 0.f);
                    vals[j] = v;
                }
                if (OSPLIT) {
                    float* ph_ = o0 + (size_t)m * HID + cb;
                    float* pl_ = o1p + (size_t)m * HID + cb;
#pragma unroll
                    for (int j = 0; j < 8; j++) {
                        float4 vh, vl;
                        split_tf32(vals[j * 4 + 0], vh.x, vl.x);
                        split_tf32(vals[j * 4 + 1], vh.y, vl.y);
                        split_tf32(vals[j * 4 + 2], vh.z, vl.z);
                        split_tf32(vals[j * 4 + 3], vh.w, vl.w);
                        *reinterpret_cast<float4*>(ph_ + j * 4) = vh;
                        *reinterpret_cast<float4*>(pl_ + j * 4) = vl;
                    }
                } else {
                    float* out = (mat == 0) ? o0 : (mat == 1) ? o1p : o2p;
                    float* po;
                    if (LAYOUT == 0) {
                        po = out + (size_t)m * HID + cb;
                    } else {
                        int b = m / LSEQ, l = m % LSEQ;
                        int h = cb >> 6, d0 = cb & 63;
                        po = out + ((size_t)(b * NHEAD + h) * LSEQ + l) * DHEAD + d0;
                    }
#pragma unroll
                    for (int j = 0; j < 8; j++) {
                        *reinterpret_cast<float4*>(po + j * 4) =
                            make_float4(vals[j * 4], vals[j * 4 + 1],
                                        vals[j * 4 + 2], vals[j * 4 + 3]);
                    }
                }
            }
        }
        TC_FENCE_BEFORE();
    }
    __syncthreads();
    if (wid == 0) TC_DEALLOC(tmem, 256);
#else
    // naive fallback (family PTX pass; exact sm_103a cubin always preferred on GB300)
    const int tid = threadIdx.x;
    const int block_m = blockIdx.x * 128;
    for (int e = tid; e < 128 * 128; e += 256) {
        int mi = e >> 7, n = e & 127;
        int m = block_m + mi;
        if (m >= M) continue;
        float acc = 0.f;
        for (int k = 0; k < KDIM; k++) {
            int addr;
            if (MODE == 0) {
                addr = m * KDIM + k;
            } else if (MODE == 1) {
                int b = m / (H1H * H1W), r = m % (H1H * H1W);
                int s = k >> 4, ic = k & 15;
                addr = ((b * TLEN + r / H1W + (s >> 2)) * SCL + (r % H1W) + (s & 3)) * NFEAT + ic;
            } else {
                int b = m / LSEQ, r = m % LSEQ;
                int s = k >> 7, ic = k & 127;
                addr = ((b * H1H + r / H2W + (s >> 2)) * H1W + (r % H2W) + (s & 3)) * HID + ic;
            }
            float a = Ah[addr] + Al[addr];
            float b_ = Bh[n * KDIM + k] + Bl[n * KDIM + k];
            acc += a * b_;
        }
        acc += bias[n];
        if (RELU) acc = fmaxf(acc, 0.f);
        if (OSPLIT) {
            float hh, ll;
            split_tf32(acc, hh, ll);
            o0[(size_t)m * HID + n] = hh;
            o1p[(size_t)m * HID + n] = ll;
        } else {
            float* out = (mat == 0) ? o0 : (mat == 1) ? o1p : o2p;
            if (LAYOUT == 0) {
                out[(size_t)m * HID + n] = acc;
            } else {
                int b = m / LSEQ, l = m % LSEQ;
                int h = n >> 6, d = n & 63;
                out[((size_t)(b * NHEAD + h) * LSEQ + l) * DHEAD + d] = acc;
            }
        }
    }
#endif
}

// ---------------- helpers ----------------
__device__ __forceinline__ float warp_sum(float v) {
    v += __shfl_xor_sync(0xffffffffu, v, 16);
    v += __shfl_xor_sync(0xffffffffu, v, 8);
    v += __shfl_xor_sync(0xffffffffu, v, 4);
    v += __shfl_xor_sync(0xffffffffu, v, 2);
    v += __shfl_xor_sync(0xffffffffu, v, 1);
    return v;
}

// ---------------- sampled scores -> M ----------------
__global__ void sampled_m_kernel(const float* __restrict__ Q, const float* __restrict__ K,
                                 const int* __restrict__ idxs, float* __restrict__ Mout) {
    int gwarp = (blockIdx.x * blockDim.x + threadIdx.x) >> 5;
    int lane = threadIdx.x & 31;
    if (gwarp >= BHCNT * LSEQ) return;
    int bh = gwarp / LSEQ;
    int l  = gwarp % LSEQ;
    const float* q = Q + (size_t)gwarp * DHEAD;
    float q0 = q[lane * 2], q1 = q[lane * 2 + 1];
    const float* Kb = K + (size_t)bh * LSEQ * DHEAD;
    float mx = NEG_INF, sm = 0.f;
#pragma unroll 1
    for (int u = 0; u < UTOP; u += 8) {
        float d[8];
#pragma unroll
        for (int j = 0; j < 8; j++) {
            int ki = __ldg(&idxs[l * UTOP + u + j]);
            const float* kr = Kb + (size_t)ki * DHEAD;
            d[j] = q0 * kr[lane * 2] + q1 * kr[lane * 2 + 1];
        }
#pragma unroll
        for (int j = 0; j < 8; j++) d[j] = warp_sum(d[j]);
#pragma unroll
        for (int j = 0; j < 8; j++) { mx = fmaxf(mx, d[j]); sm += d[j]; }
    }
    if (lane == 0) Mout[gwarp] = mx - sm / (float)LSEQ;
}

// ---------------- top-40 per (b,h) ----------------
__global__ void topk_kernel(const float* __restrict__ Min, int* __restrict__ Mtop) {
    __shared__ float vals[LSEQ];
    __shared__ float rv[256];
    __shared__ int   ri[256];
    int bh = blockIdx.x;
    int tid = threadIdx.x;
    for (int j = tid; j < LSEQ; j += 256) vals[j] = Min[bh * LSEQ + j];
    __syncthreads();
    for (int it = 0; it < UTOP; it++) {
        float best = NEG_INF;
        int bi = LSEQ;
        for (int j = tid; j < LSEQ; j += 256) {
            float v = vals[j];
            if (v > best) { best = v; bi = j; }
        }
        rv[tid] = best; ri[tid] = bi;
        __syncthreads();
        for (int s = 128; s > 0; s >>= 1) {
            if (tid < s) {
                float vo = rv[tid + s]; int io = ri[tid + s];
                if (vo > rv[tid] || (vo == rv[tid] && io < ri[tid])) { rv[tid] = vo; ri[tid] = io; }
            }
            __syncthreads();
        }
        if (tid == 0) {
            Mtop[bh * UTOP + it] = ri[0];
            vals[ri[0]] = NEG_INF;
        }
        __syncthreads();
    }
}

// ---------------- V mean per (b,h) ----------------
#define VSLICE 377    // LSEQ/4
__global__ void vmean_kernel(const float* __restrict__ V, float* __restrict__ vmean) {
    __shared__ float part[4][DHEAD];
    int bh = blockIdx.x;
    int tid = threadIdx.x;
    int d = tid & 63;
    int sl = tid >> 6;
    const float* Vb = V + (size_t)bh * LSEQ * DHEAD;
    float s = 0.f;
    int beg = sl * VSLICE, end = beg + VSLICE;
    for (int l = beg; l < end; l++) s += Vb[(size_t)l * DHEAD + d];
    part[sl][d] = s;
    __syncthreads();
    if (tid < DHEAD)
        vmean[bh * DHEAD + tid] =
            (part[0][tid] + part[1][tid] + part[2][tid] + part[3][tid]) / (float)LSEQ;
}

// ---------------- attention: 1 block (4 warps) per selected query ----------------
__global__ void attn_kernel(const float* __restrict__ Q, const float* __restrict__ K,
                            const float* __restrict__ V, const int* __restrict__ Mtop,
                            float* __restrict__ upd) {
    __shared__ float s_m[4], s_s[4], s_a[4][DHEAD];
    int qi = blockIdx.x;
    int bh = qi / UTOP;
    int l = Mtop[qi];
    int wid = threadIdx.x >> 5;
    int lane = threadIdx.x & 31;
    const float* q = Q + ((size_t)bh * LSEQ + l) * DHEAD;
    float q0 = q[lane * 2], q1 = q[lane * 2 + 1];
    const float* Kb = K + (size_t)bh * LSEQ * DHEAD;
    const float* Vb = V + (size_t)bh * LSEQ * DHEAD;

    int beg = wid * VSLICE, end = beg + VSLICE;
    float m[4], sa[4], a0[4], a1[4];
#pragma unroll
    for (int j = 0; j < 4; j++) { m[j] = NEG_INF; sa[j] = 0.f; a0[j] = 0.f; a1[j] = 0.f; }

#pragma unroll 1
    for (int k0 = beg; k0 < end; k0 += 4) {
        float d[4], v0[4], v1[4];
#pragma unroll
        for (int j = 0; j < 4; j++) {
            int kk = (k0 + j < end) ? (k0 + j) : beg;
            const float* kr = Kb + (size_t)kk * DHEAD;
            d[j] = q0 * kr[lane * 2] + q1 * kr[lane * 2 + 1];
        }
#pragma unroll
        for (int j = 0; j < 4; j++) d[j] = warp_sum(d[j]) * 0.125f;
#pragma unroll
        for (int j = 0; j < 4; j++) {
            int kk = (k0 + j < end) ? (k0 + j) : beg;
            const float* vr = Vb + (size_t)kk * DHEAD;
            v0[j] = vr[lane * 2];
            v1[j] = vr[lane * 2 + 1];
        }
#pragma unroll
        for (int j = 0; j < 4; j++) {
            if (k0 + j >= end) continue;
            float nm = fmaxf(m[j], d[j]);
            float c = __expf(m[j] - nm);
            float p = __expf(d[j] - nm);
            sa[j] = sa[j] * c + p;
            a0[j] = a0[j] * c + p * v0[j];
            a1[j] = a1[j] * c + p * v1[j];
            m[j] = nm;
        }
    }
    float M0 = fmaxf(fmaxf(m[0], m[1]), fmaxf(m[2], m[3]));
    float S = 0.f, A0 = 0.f, A1 = 0.f;
#pragma unroll
    for (int j = 0; j < 4; j++) {
        float c = __expf(m[j] - M0);
        S += sa[j] * c;
        A0 += a0[j] * c;
        A1 += a1[j] * c;
    }
    if (lane == 0) { s_m[wid] = M0; s_s[wid] = S; }
    s_a[wid][lane * 2] = A0;
    s_a[wid][lane * 2 + 1] = A1;
    __syncthreads();
    if (wid == 0) {
        float MM = fmaxf(fmaxf(s_m[0], s_m[1]), fmaxf(s_m[2], s_m[3]));
        float c0 = __expf(s_m[0] - MM), c1 = __expf(s_m[1] - MM);
        float c2 = __expf(s_m[2] - MM), c3 = __expf(s_m[3] - MM);
        float SS = s_s[0] * c0 + s_s[1] * c1 + s_s[2] * c2 + s_s[3] * c3;
        float inv = 1.f / SS;
        int d0 = lane * 2;
        float r0 = (s_a[0][d0] * c0 + s_a[1][d0] * c1 + s_a[2][d0] * c2 + s_a[3][d0] * c3) * inv;
        int d1 = d0 + 1;
        float r1 = (s_a[0][d1] * c0 + s_a[1][d1] * c1 + s_a[2][d1] * c2 + s_a[3][d1] * c3) * inv;
        upd[(size_t)qi * DHEAD + d0] = r0;
        upd[(size_t)qi * DHEAD + d1] = r1;
    }
}

// ---------------- ctx fill (broadcast vmean, hi/lo split) ----------------
__global__ void fill_ctx_kernel(const float* __restrict__ vmean,
                                float* __restrict__ ctxh, float* __restrict__ ctxl) {
    int idx = blockIdx.x * blockDim.x + threadIdx.x;
    if (idx >= M2 * HID) return;
    int c = idx & 127;
    int m = idx >> 7;
    int b = m / LSEQ;
    int h = c >> 6, d = c & 63;
    float v = vmean[(b * NHEAD + h) * DHEAD + d];
    float hh, ll;
    split_tf32(v, hh, ll);
    ctxh[idx] = hh;
    ctxl[idx] = ll;
}

// ---------------- scatter upd rows (hi/lo split) ----------------
__global__ void scatter_kernel(const float* __restrict__ upd, const int* __restrict__ Mtop,
                               float* __restrict__ ctxh, float* __restrict__ ctxl) {
    int idx = blockIdx.x * blockDim.x + threadIdx.x;
    if (idx >= BHCNT * UTOP * DHEAD) return;
    int d = idx & 63;
    int r = idx >> 6;
    int bh = r / UTOP;
    int b = bh / NHEAD, h = bh % NHEAD;
    int l = Mtop[r];
    float v = upd[idx];
    float hh, ll;
    split_tf32(v, hh, ll);
    size_t o = ((size_t)(b * LSEQ + l)) * HID + h * DHEAD + d;
    ctxh[o] = hh;
    ctxl[o] = ll;
}

// ---------------- launch ----------------
extern "C" void kernel_launch(void* const* d_in, const int* in_sizes, int n_in,
                              void* d_out, int out_size) {
    const float* x       = (const float*)d_in[0];
    const float* conv1_w = (const float*)d_in[1];
    const float* conv1_b = (const float*)d_in[2];
    const float* conv2_w = (const float*)d_in[3];
    const float* conv2_b = (const float*)d_in[4];
    const float* wq = (const float*)d_in[5];
    const float* bq = (const float*)d_in[6];
    const float* wk = (const float*)d_in[7];
    const float* bk = (const float*)d_in[8];
    const float* wv = (const float*)d_in[9];
    const float* bv = (const float*)d_in[10];
    const float* wo = (const float*)d_in[11];
    const float* bo = (const float*)d_in[12];
    const int* index_sample = (const int*)d_in[13];
    float* out = (float*)d_out;

    float *xh, *xl, *h1h, *h1l, *seqh, *seql, *ctxh, *ctxl;
    float *Qp, *Kp, *Vp, *Mv, *updv, *vmeanv;
    float *B1h, *B1l, *B2h, *B2l, *wqkvTh, *wqkvTl, *woTh, *woTl;
    int *mtop;
    cudaGetSymbolAddress((void**)&xh, g_xh);
    cudaGetSymbolAddress((void**)&xl, g_xl);
    cudaGetSymbolAddress((void**)&h1h, g_h1h);
    cudaGetSymbolAddress((void**)&h1l, g_h1l);
    cudaGetSymbolAddress((void**)&seqh, g_seqh);
    cudaGetSymbolAddress((void**)&seql, g_seql);
    cudaGetSymbolAddress((void**)&ctxh, g_ctxh);
    cudaGetSymbolAddress((void**)&ctxl, g_ctxl);
    cudaGetSymbolAddress((void**)&Qp, g_Q);
    cudaGetSymbolAddress((void**)&Kp, g_K);
    cudaGetSymbolAddress((void**)&Vp, g_V);
    cudaGetSymbolAddress((void**)&Mv, g_M);
    cudaGetSymbolAddress((void**)&mtop, g_Mtop);
    cudaGetSymbolAddress((void**)&updv, g_upd);
    cudaGetSymbolAddress((void**)&vmeanv, g_vmean);
    cudaGetSymbolAddress((void**)&B1h, g_B1h);
    cudaGetSymbolAddress((void**)&B1l, g_B1l);
    cudaGetSymbolAddress((void**)&B2h, g_B2h);
    cudaGetSymbolAddress((void**)&B2l, g_B2l);
    cudaGetSymbolAddress((void**)&wqkvTh, g_wqkvTh);
    cudaGetSymbolAddress((void**)&wqkvTl, g_wqkvTl);
    cudaGetSymbolAddress((void**)&woTh, g_woTh);
    cudaGetSymbolAddress((void**)&woTl, g_woTl);

    cudaFuncSetAttribute((const void*)gemm_tc_kernel<1, K1, true, 1, 0, true>,
                         cudaFuncAttributeMaxDynamicSharedMemorySize, GEMM_SMEM_BYTES);
    cudaFuncSetAttribute((const void*)gemm_tc_kernel<2, K2, true, 1, 0, true>,
                         cudaFuncAttributeMaxDynamicSharedMemorySize, GEMM_SMEM_BYTES);
    cudaFuncSetAttribute((const void*)gemm_tc_kernel<0, HID, false, 3, 1, false>,
                         cudaFuncAttributeMaxDynamicSharedMemorySize, GEMM_SMEM_BYTES);
    cudaFuncSetAttribute((const void*)gemm_tc_kernel<0, HID, false, 1, 0, false>,
                         cudaFuncAttributeMaxDynamicSharedMemorySize, GEMM_SMEM_BYTES);

    // fused prep (remap + pre-split weights and x)
    prep_kernel<<<(PREP_S4 + 255) / 256, 256>>>(x, conv1_w, conv2_w, wq, wk, wv, wo,
                                                xh, xl, B1h, B1l, B2h, B2l,
                                                wqkvTh, wqkvTl, woTh, woTl);

    // conv1 -> h1 hi/lo (NHWC row-major), relu
    gemm_tc_kernel<1, K1, true, 1, 0, true>
        <<<(M1 + 127) / 128, 256, GEMM_SMEM_BYTES>>>(xh, xl, B1h, B1l,
                                                     conv1_b, conv1_b, conv1_b,
                                                     h1h, h1l, h1l, M1);

    // conv2 -> seq hi/lo, relu
    gemm_tc_kernel<2, K2, true, 1, 0, true>
        <<<(M2 + 127) / 128, 256, GEMM_SMEM_BYTES>>>(h1h, h1l, B2h, B2l,
                                                     conv2_b, conv2_b, conv2_b,
                                                     seqh, seql, seql, M2);

    // QKV: grid.y = 3, head layout
    gemm_tc_kernel<0, HID, false, 3, 1, false>
        <<<dim3((M2 + 127) / 128, 3), 256, GEMM_SMEM_BYTES>>>(seqh, seql, wqkvTh, wqkvTl,
                                                              bq, bk, bv, Qp, Kp, Vp, M2);

    // sampled scores -> M
    {
        int warps = BHCNT * LSEQ;
        sampled_m_kernel<<<(warps + 7) / 8, 256>>>(Qp, Kp, index_sample, Mv);
    }

    topk_kernel<<<BHCNT, 256>>>(Mv, mtop);
    vmean_kernel<<<BHCNT, 256>>>(Vp, vmeanv);

    attn_kernel<<<BHCNT * UTOP, 128>>>(Qp, Kp, Vp, mtop, updv);

    fill_ctx_kernel<<<(M2 * HID + 255) / 256, 256>>>(vmeanv, ctxh, ctxl);
    scatter_kernel<<<(BHCNT * UTOP * DHEAD + 255) / 256, 256>>>(updv, mtop, ctxh, ctxl);

    // final projection
    gemm_tc_kernel<0, HID, false, 1, 0, false>
        <<<(M2 + 127) / 128, 256, GEMM_SMEM_BYTES>>>(ctxh, ctxl, woTh, woTl,
                                                     bo, bo, bo, out, out, out, M2);
}

// round 12
// speedup vs baseline: 1.0755x; 1.0332x over previous
#include <cuda_runtime.h>
#include <cstdint>
#include <math.h>

#define NEG_INF (__int_as_float(0xff800000))

// ---------------- problem constants ----------------
#define BATCH   16
#define NFEAT   16
#define TLEN    64
#define SCL     32
#define HID     128
#define FS      4
#define NHEAD   2
#define DHEAD   64

#define H1H     61
#define H1W     29
#define H2H     58
#define H2W     26
#define LSEQ    1508
#define UTOP    40

#define K1      256
#define K2      2048
#define M1      (BATCH*H1H*H1W)   // 28304
#define M2      (BATCH*LSEQ)      // 24128
#define BHCNT   (BATCH*NHEAD)     // 32

#if defined(__CUDA_ARCH_FEAT_SM103_ALL) || defined(__CUDA_ARCH_SPECIFIC__)
#define TC_PATH 1
#else
#define TC_PATH 0
#endif

// ---------------- scratch ----------------
__device__ float g_xcl[BATCH*TLEN*SCL*NFEAT];
__device__ float g_h1cl[M1*HID];
__device__ float g_seq[M2*HID];
__device__ float g_Q[BHCNT*LSEQ*DHEAD];
__device__ float g_K[BHCNT*LSEQ*DHEAD];
__device__ float g_V[BHCNT*LSEQ*DHEAD];
__device__ float g_M[BHCNT*LSEQ];
__device__ int   g_Mtop[BHCNT*UTOP];
__device__ float g_upd[BHCNT*UTOP*DHEAD];
__device__ float g_vmean[BHCNT*DHEAD];
__device__ float g_B1[HID*K1];
__device__ float g_B2[HID*K2];
__device__ float g_wqkvT[3*HID*HID];
__device__ float g_woT[HID*HID];
__device__ int   g_sel[BHCNT*LSEQ];
__device__ float g_baseout[BATCH*HID];

// ---------------- PTX helpers ----------------
__device__ __forceinline__ uint32_t smem_u32(const void* p) {
    uint32_t a;
    asm("{ .reg .u64 t; cvta.to.shared.u64 t, %1; cvt.u32.u64 %0, t; }" : "=r"(a) : "l"(p));
    return a;
}

#define TC_ALLOC(sa, n) \
    asm volatile("tcgen05.alloc.cta_group::1.sync.aligned.shared::cta.b32 [%0], %1;" \
                 :: "r"(sa), "r"(n) : "memory")
#define TC_DEALLOC(t, n) \
    asm volatile("tcgen05.dealloc.cta_group::1.sync.aligned.b32 %0, %1;" :: "r"(t), "r"(n))
#define TC_RELINQ() \
    asm volatile("tcgen05.relinquish_alloc_permit.cta_group::1.sync.aligned;")
#define TC_COMMIT(mb) \
    asm volatile("tcgen05.commit.cta_group::1.mbarrier::arrive::one.shared::cluster.b64 [%0];" \
                 :: "r"(mb) : "memory")
#define TC_FENCE_AFTER()  asm volatile("tcgen05.fence::after_thread_sync;" ::: "memory")
#define TC_FENCE_BEFORE() asm volatile("tcgen05.fence::before_thread_sync;" ::: "memory")
#define TC_WAIT_LD()      asm volatile("tcgen05.wait::ld.sync.aligned;" ::: "memory")
#define MB_INIT(mb, c) \
    asm volatile("mbarrier.init.shared.b64 [%0], %1;" :: "r"(mb), "r"(c) : "memory")
#define FENCE_ASYNC() asm volatile("fence.proxy.async.shared::cta;" ::: "memory")

#define MB_WAIT_PARITY(mbar_smem_addr, phase_parity) do { \
    uint32_t _mbar = (uint32_t)(mbar_smem_addr); \
    uint32_t _parity = (uint32_t)(phase_parity); \
    uint32_t _done; \
    asm volatile( \
        "{\n\t" \
        ".reg .pred p;\n\t" \
        "mbarrier.try_wait.parity.acquire.cta.shared::cta.b64 p, [%1], %2;\n\t" \
        "selp.b32 %0, 1, 0, p;\n\t" \
        "}" \
        : "=r"(_done) : "r"(_mbar), "r"(_parity) : "memory"); \
    if (!_done) { \
        asm volatile( \
            "{\n\t" \
            ".reg .pred P1;\n\t" \
            "WAIT_LOOP_%=:\n\t" \
            "mbarrier.try_wait.parity.acquire.cta.shared::cta.b64 P1, [%0], %1, 0x989680;\n\t" \
            "@P1 bra.uni WAIT_DONE_%=;\n\t" \
            "bra.uni WAIT_LOOP_%=;\n\t" \
            "WAIT_DONE_%=:\n\t" \
            "}" \
            :: "r"(_mbar), "r"(_parity) : "memory"); \
    } \
} while(0)

#define TC_LD_X32(r, tmem_addr) \
    asm volatile( \
        "tcgen05.ld.sync.aligned.32x32b.x32.b32 " \
        "{%0, %1, %2, %3, %4, %5, %6, %7, " \
        " %8, %9, %10, %11, %12, %13, %14, %15, " \
        " %16, %17, %18, %19, %20, %21, %22, %23, " \
        " %24, %25, %26, %27, %28, %29, %30, %31}, [%32];" \
        : "=r"((r)[0]),  "=r"((r)[1]),  "=r"((r)[2]),  "=r"((r)[3]), \
          "=r"((r)[4]),  "=r"((r)[5]),  "=r"((r)[6]),  "=r"((r)[7]), \
          "=r"((r)[8]),  "=r"((r)[9]),  "=r"((r)[10]), "=r"((r)[11]), \
          "=r"((r)[12]), "=r"((r)[13]), "=r"((r)[14]), "=r"((r)[15]), \
          "=r"((r)[16]), "=r"((r)[17]), "=r"((r)[18]), "=r"((r)[19]), \
          "=r"((r)[20]), "=r"((r)[21]), "=r"((r)[22]), "=r"((r)[23]), \
          "=r"((r)[24]), "=r"((r)[25]), "=r"((r)[26]), "=r"((r)[27]), \
          "=r"((r)[28]), "=r"((r)[29]), "=r"((r)[30]), "=r"((r)[31]) \
        : "r"(tmem_addr))

#if TC_PATH
__device__ __forceinline__ void mma_tf32_ss(uint32_t d_tmem, uint64_t a_desc,
                                            uint64_t b_desc, uint32_t idesc, bool accum) {
    uint32_t en = accum ? 1u : 0u;
    asm volatile(
        "{\n\t"
        ".reg .pred p;\n\t"
        "setp.ne.u32 p, %4, 0;\n\t"
        "tcgen05.mma.cta_group::1.kind::tf32 [%0], %1, %2, %3, p;\n\t"
        "}"
        :: "r"(d_tmem), "l"(a_desc), "l"(b_desc), "r"(idesc), "r"(en)
        : "memory");
}
#endif

// SW128 SMEM descriptor
__device__ __forceinline__ uint64_t make_desc(uint32_t addr) {
    return ((uint64_t)2 << 61) | ((uint64_t)1 << 46) | ((uint64_t)64 << 32)
         | ((uint64_t)1 << 16) | (uint64_t)((addr >> 4) & 0x3FFF);
}

__device__ __forceinline__ uint32_t swz128(uint32_t off) {
    return off ^ ((off >> 3) & 0x70);
}

__device__ __forceinline__ void split_tf32(float v, float& hi, float& lo) {
    uint32_t h;
    asm("cvt.rna.tf32.f32 %0, %1;" : "=r"(h) : "f"(v));
    hi = __uint_as_float(h);
    lo = v - hi;
}

#define TF32_IDESC ((1u << 4) | (2u << 7) | (2u << 10) | (16u << 17) | (8u << 24))

// ---------------- fused prep kernel ----------------
#define PREP_S0 (BATCH*NFEAT*TLEN*SCL)
#define PREP_S1 (PREP_S0 + HID*K1)
#define PREP_S2 (PREP_S1 + HID*K2)
#define PREP_S3 (PREP_S2 + 3*HID*HID)
#define PREP_S4 (PREP_S3 + HID*HID)
__global__ void prep_kernel(const float* __restrict__ x,
                            const float* __restrict__ c1w, const float* __restrict__ c2w,
                            const float* __restrict__ wq, const float* __restrict__ wk,
                            const float* __restrict__ wv, const float* __restrict__ wo,
                            float* __restrict__ xcl, float* __restrict__ B1,
                            float* __restrict__ B2, float* __restrict__ wqkvT,
                            float* __restrict__ woT) {
    int idx = blockIdx.x * blockDim.x + threadIdx.x;
    if (idx < PREP_S0) {
        int w = idx % SCL;
        int h = (idx / SCL) % TLEN;
        int c = (idx / (SCL * TLEN)) % NFEAT;
        int b = idx / (SCL * TLEN * NFEAT);
        xcl[((b * TLEN + h) * SCL + w) * NFEAT + c] = x[idx];
    } else if (idx < PREP_S1) {
        int i = idx - PREP_S0;
        int n = i / K1, k = i % K1;
        int ic = k / 16, s = k % 16;
        B1[n * K1 + s * NFEAT + ic] = c1w[i];
    } else if (idx < PREP_S2) {
        int i = idx - PREP_S1;
        int n = i / K2, k = i % K2;
        int ic = k / 16, s = k % 16;
        B2[n * K2 + s * HID + ic] = c2w[i];
    } else if (idx < PREP_S3) {
        int i = idx - PREP_S2;
        int mat = i / (HID * HID);
        int r = i % (HID * HID);
        int a = r / HID, b = r % HID;
        const float* w = (mat == 0) ? wq : (mat == 1) ? wk : wv;
        wqkvT[mat * HID * HID + b * HID + a] = w[r];
    } else if (idx < PREP_S4) {
        int i = idx - PREP_S3;
        int a = i / HID, b = i % HID;
        woT[b * HID + a] = wo[i];
    }
}

// ---------------- tcgen05 3xTF32 GEMM (R8 config, locked) ----------------
#define GEMM_SMEM_BYTES (79872)

template<int MODE, int KDIM, bool RELU, int NMAT, int LAYOUT>
__global__ void __launch_bounds__(256, 2)
gemm_tc_kernel(const float* __restrict__ Ain, const float* __restrict__ BwAll,
               const float* __restrict__ b0, const float* __restrict__ b1p,
               const float* __restrict__ b2p,
               float* __restrict__ o0, float* __restrict__ o1p, float* __restrict__ o2p,
               int M) {
    const int mat = (NMAT > 1) ? blockIdx.y : 0;
    const float* Bw = BwAll + (size_t)mat * HID * KDIM;
    const float* bias = (mat == 0) ? b0 : (mat == 1) ? b1p : b2p;
    float* out = (mat == 0) ? o0 : (mat == 1) ? o1p : o2p;

#if TC_PATH
    extern __shared__ char dynraw[];
    __shared__ uint32_t s_tmem[1];
    __shared__ __align__(8) unsigned long long s_mbar[1];

    const int tid = threadIdx.x;
    const int wid = tid >> 5;
    const int lane = tid & 31;
    const int block_m = blockIdx.x * 128;

    uint32_t dynb32 = smem_u32(dynraw);
    uint32_t smem_base = (dynb32 + 1023u) & ~1023u;
    char* dbase = dynraw + (smem_base - dynb32);
    uint32_t mbar0 = smem_u32(&s_mbar[0]);

    if (wid == 0) {
        TC_ALLOC(smem_u32(s_tmem), 256);
        TC_RELINQ();
    }
    if (tid == 0) MB_INIT(mbar0, 1);
    __syncthreads();
    uint32_t tmem;
    asm volatile("ld.shared.b32 %0, [%1];" : "=r"(tmem) : "r"(smem_u32(s_tmem)));

    const int quad = tid & 7;
    int rowi[4], abase[4];
    bool aok[4];
#pragma unroll
    for (int i = 0; i < 4; i++) {
        rowi[i] = i * 32 + (tid >> 3);
        int m = block_m + rowi[i];
        aok[i] = (m < M);
        int mc = aok[i] ? m : 0;
        if (MODE == 0) {
            abase[i] = mc * KDIM;
        } else if (MODE == 1) {
            int b = mc / (H1H * H1W);
            int r = mc % (H1H * H1W);
            abase[i] = ((b * TLEN + r / H1W) * SCL + (r % H1W)) * NFEAT;
        } else {
            int b = mc / LSEQ;
            int r = mc % LSEQ;
            abase[i] = ((b * H1H + r / H2W) * H1W + (r % H2W)) * HID;
        }
    }
    uint32_t swz[4];
#pragma unroll
    for (int i = 0; i < 4; i++)
        swz[i] = swz128((uint32_t)rowi[i] * 128u + (uint32_t)quad * 16u);

    float4 areg[4], breg[4];
    auto load_regs = [&](int c) {
        const int kq = c * 32 + quad * 4;
#pragma unroll
        for (int i = 0; i < 4; i++) {
            areg[i] = make_float4(0.f, 0.f, 0.f, 0.f);
            if (aok[i]) {
                int addr;
                if (MODE == 0) {
                    addr = abase[i] + kq;
                } else if (MODE == 1) {
                    int s = kq >> 4, ic = kq & 15;
                    addr = abase[i] + (((s >> 2) * SCL) + (s & 3)) * NFEAT + ic;
                } else {
                    int s = kq >> 7, ic = kq & 127;
                    addr = abase[i] + (((s >> 2) * H1W) + (s & 3)) * HID + ic;
                }
                areg[i] = *reinterpret_cast<const float4*>(Ain + addr);
            }
            breg[i] = *reinterpret_cast<const float4*>(Bw + rowi[i] * KDIM + kq);
        }
    };
    auto store_tiles = [&]() {
        char* Ahi = dbase;
        char* Alo = Ahi + 16384;
        char* Bhi = Ahi + 32768;
        char* Blo = Ahi + 49152;
#pragma unroll
        for (int i = 0; i < 4; i++) {
            float4 h4, l4;
            split_tf32(areg[i].x, h4.x, l4.x);
            split_tf32(areg[i].y, h4.y, l4.y);
            split_tf32(areg[i].z, h4.z, l4.z);
            split_tf32(areg[i].w, h4.w, l4.w);
            *reinterpret_cast<float4*>(Ahi + swz[i]) = h4;
            *reinterpret_cast<float4*>(Alo + swz[i]) = l4;
            split_tf32(breg[i].x, h4.x, l4.x);
            split_tf32(breg[i].y, h4.y, l4.y);
            split_tf32(breg[i].z, h4.z, l4.z);
            split_tf32(breg[i].w, h4.w, l4.w);
            *reinterpret_cast<float4*>(Bhi + swz[i]) = h4;
            *reinterpret_cast<float4*>(Blo + swz[i]) = l4;
        }
    };

    const int NC = KDIM / 32;
    int ph = 0;
    load_regs(0);

    for (int c = 0; c < NC; c++) {
        if (c > 0) {
            MB_WAIT_PARITY(mbar0, ph);
            ph ^= 1;
        }
        store_tiles();
        if (c + 1 < NC) load_regs(c + 1);
        FENCE_ASYNC();
        __syncthreads();
        if (tid == 0) {
            uint64_t dah = make_desc(smem_base);
            uint64_t dal = make_desc(smem_base + 16384);
            uint64_t dbh = make_desc(smem_base + 32768);
            uint64_t dbl = make_desc(smem_base + 49152);
#pragma unroll
            for (int s = 0; s < 4; s++) {
                uint64_t o = (uint64_t)(s * 2);
                mma_tf32_ss(tmem, dah + o, dbh + o, TF32_IDESC, !(c == 0 && s == 0));
                mma_tf32_ss(tmem, dah + o, dbl + o, TF32_IDESC, true);
                mma_tf32_ss(tmem, dal + o, dbh + o, TF32_IDESC, true);
            }
            TC_COMMIT(mbar0);
        }
    }
    MB_WAIT_PARITY(mbar0, ph);
    TC_FENCE_AFTER();
    __syncthreads();

    if (wid < 4) {
        int m = block_m + wid * 32 + lane;
#pragma unroll
        for (int cb = 0; cb < 128; cb += 32) {
            uint32_t r[32];
            TC_LD_X32(r, tmem + cb);
            TC_WAIT_LD();
            if (m < M) {
                float vals[32];
#pragma unroll
                for (int j = 0; j < 32; j++) {
                    float v = __uint_as_float(r[j]) + __ldg(&bias[cb + j]);
                    if (RELU) v = fmaxf(v, 0.f);
                    vals[j] = v;
                }
                float* po;
                if (LAYOUT == 0) {
                    po = out + (size_t)m * HID + cb;
                } else {
                    int b = m / LSEQ, l = m % LSEQ;
                    int h = cb >> 6, d0 = cb & 63;
                    po = out + ((size_t)(b * NHEAD + h) * LSEQ + l) * DHEAD + d0;
                }
#pragma unroll
                for (int j = 0; j < 8; j++) {
                    *reinterpret_cast<float4*>(po + j * 4) =
                        make_float4(vals[j * 4], vals[j * 4 + 1], vals[j * 4 + 2], vals[j * 4 + 3]);
                }
            }
        }
        TC_FENCE_BEFORE();
    }
    __syncthreads();
    if (wid == 0) TC_DEALLOC(tmem, 256);
#else
    // naive fallback (family PTX pass; exact sm_103a cubin preferred on GB300)
    const int tid = threadIdx.x;
    const int block_m = blockIdx.x * 128;
    for (int e = tid; e < 128 * 128; e += 256) {
        int mi = e >> 7, n = e & 127;
        int m = block_m + mi;
        if (m >= M) continue;
        float acc = 0.f;
        for (int k = 0; k < KDIM; k++) {
            float a;
            if (MODE == 0) {
                a = Ain[(size_t)m * KDIM + k];
            } else if (MODE == 1) {
                int b = m / (H1H * H1W), r = m % (H1H * H1W);
                int s = k >> 4, ic = k & 15;
                a = Ain[((b * TLEN + r / H1W + (s >> 2)) * SCL + (r % H1W) + (s & 3)) * NFEAT + ic];
            } else {
                int b = m / LSEQ, r = m % LSEQ;
                int s = k >> 7, ic = k & 127;
                a = Ain[((b * H1H + r / H2W + (s >> 2)) * H1W + (r % H2W) + (s & 3)) * HID + ic];
            }
            acc += a * Bw[n * KDIM + k];
        }
        acc += bias[n];
        if (RELU) acc = fmaxf(acc, 0.f);
        if (LAYOUT == 0) {
            out[(size_t)m * HID + n] = acc;
        } else {
            int b = m / LSEQ, l = m % LSEQ;
            int h = n >> 6, d = n & 63;
            out[((size_t)(b * NHEAD + h) * LSEQ + l) * DHEAD + d] = acc;
        }
    }
#endif
}

// ---------------- helpers ----------------
__device__ __forceinline__ float warp_sum(float v) {
    v += __shfl_xor_sync(0xffffffffu, v, 16);
    v += __shfl_xor_sync(0xffffffffu, v, 8);
    v += __shfl_xor_sync(0xffffffffu, v, 4);
    v += __shfl_xor_sync(0xffffffffu, v, 2);
    v += __shfl_xor_sync(0xffffffffu, v, 1);
    return v;
}

// ---------------- sampled scores -> M ----------------
__global__ void sampled_m_kernel(const float* __restrict__ Q, const float* __restrict__ K,
                                 const int* __restrict__ idxs, float* __restrict__ Mout) {
    int gwarp = (blockIdx.x * blockDim.x + threadIdx.x) >> 5;
    int lane = threadIdx.x & 31;
    if (gwarp >= BHCNT * LSEQ) return;
    int bh = gwarp / LSEQ;
    int l  = gwarp % LSEQ;
    const float* q = Q + (size_t)gwarp * DHEAD;
    float q0 = q[lane * 2], q1 = q[lane * 2 + 1];
    const float* Kb = K + (size_t)bh * LSEQ * DHEAD;
    float mx = NEG_INF, sm = 0.f;
#pragma unroll 1
    for (int u = 0; u < UTOP; u += 8) {
        float d[8];
#pragma unroll
        for (int j = 0; j < 8; j++) {
            int ki = __ldg(&idxs[l * UTOP + u + j]);
            const float* kr = Kb + (size_t)ki * DHEAD;
            d[j] = q0 * kr[lane * 2] + q1 * kr[lane * 2 + 1];
        }
#pragma unroll
        for (int j = 0; j < 8; j++) d[j] = warp_sum(d[j]);
#pragma unroll
        for (int j = 0; j < 8; j++) { mx = fmaxf(mx, d[j]); sm += d[j]; }
    }
    if (lane == 0) Mout[gwarp] = mx - sm / (float)LSEQ;
}

// ---------------- top-40 via bitonic sort of 2048 keys ----------------
// key = (~sortable(v)) << 32 | index  -> ascending u64 sort gives
// descending value, ascending index on ties (matches lax.top_k).
#define SORTN 2048
__global__ void __launch_bounds__(256)
topk_kernel(const float* __restrict__ Min, int* __restrict__ Mtop) {
    __shared__ unsigned long long keys[SORTN];
    int bh = blockIdx.x;
    int tid = threadIdx.x;
    for (int j = tid; j < SORTN; j += 256) {
        unsigned long long key;
        if (j < LSEQ) {
            uint32_t b = __float_as_uint(Min[bh * LSEQ + j]);
            uint32_t s = (b & 0x80000000u) ? ~b : (b | 0x80000000u);
            key = ((unsigned long long)(~s) << 32) | (uint32_t)j;
        } else {
            key = 0xFFFFFFFFFFFFFFFFull;   // sorts last
        }
        keys[j] = key;
    }
    __syncthreads();
    for (int k = 2; k <= SORTN; k <<= 1) {
        for (int j = k >> 1; j > 0; j >>= 1) {
#pragma unroll 4
            for (int t = tid; t < SORTN / 2; t += 256) {
                int i = ((t / j) * j * 2) + (t % j);
                int l2 = i + j;
                bool up = ((i & k) == 0);
                unsigned long long a = keys[i], b = keys[l2];
                if ((a > b) == up) { keys[i] = b; keys[l2] = a; }
            }
            __syncthreads();
        }
    }
    if (tid < UTOP)
        Mtop[bh * UTOP + tid] = (int)(keys[tid] & 0xFFFFFFFFull);
}

// ---------------- V mean per (b,h) ----------------
#define VSLICE 377    // LSEQ/4
__global__ void vmean_kernel(const float* __restrict__ V, float* __restrict__ vmean) {
    __shared__ float part[4][DHEAD];
    int bh = blockIdx.x;
    int tid = threadIdx.x;
    int d = tid & 63;
    int sl = tid >> 6;
    const float* Vb = V + (size_t)bh * LSEQ * DHEAD;
    float s = 0.f;
    int beg = sl * VSLICE, end = beg + VSLICE;
    for (int l = beg; l < end; l++) s += Vb[(size_t)l * DHEAD + d];
    part[sl][d] = s;
    __syncthreads();
    if (tid < DHEAD)
        vmean[bh * DHEAD + tid] =
            (part[0][tid] + part[1][tid] + part[2][tid] + part[3][tid]) / (float)LSEQ;
}

// ---------------- attention: 1 block (4 warps) per selected query ----------------
__global__ void attn_kernel(const float* __restrict__ Q, const float* __restrict__ K,
                            const float* __restrict__ V, const int* __restrict__ Mtop,
                            float* __restrict__ upd) {
    __shared__ float s_m[4], s_s[4], s_a[4][DHEAD];
    int qi = blockIdx.x;
    int bh = qi / UTOP;
    int l = Mtop[qi];
    int wid = threadIdx.x >> 5;
    int lane = threadIdx.x & 31;
    const float* q = Q + ((size_t)bh * LSEQ + l) * DHEAD;
    float q0 = q[lane * 2], q1 = q[lane * 2 + 1];
    const float* Kb = K + (size_t)bh * LSEQ * DHEAD;
    const float* Vb = V + (size_t)bh * LSEQ * DHEAD;

    int beg = wid * VSLICE, end = beg + VSLICE;
    float m[4], sa[4], a0[4], a1[4];
#pragma unroll
    for (int j = 0; j < 4; j++) { m[j] = NEG_INF; sa[j] = 0.f; a0[j] = 0.f; a1[j] = 0.f; }

#pragma unroll 1
    for (int k0 = beg; k0 < end; k0 += 4) {
        float d[4], v0[4], v1[4];
#pragma unroll
        for (int j = 0; j < 4; j++) {
            int kk = (k0 + j < end) ? (k0 + j) : beg;
            const float* kr = Kb + (size_t)kk * DHEAD;
            d[j] = q0 * kr[lane * 2] + q1 * kr[lane * 2 + 1];
        }
#pragma unroll
        for (int j = 0; j < 4; j++) d[j] = warp_sum(d[j]) * 0.125f;
#pragma unroll
        for (int j = 0; j < 4; j++) {
            int kk = (k0 + j < end) ? (k0 + j) : beg;
            const float* vr = Vb + (size_t)kk * DHEAD;
            v0[j] = vr[lane * 2];
            v1[j] = vr[lane * 2 + 1];
        }
#pragma unroll
        for (int j = 0; j < 4; j++) {
            if (k0 + j >= end) continue;
            float nm = fmaxf(m[j], d[j]);
            float c = __expf(m[j] - nm);
            float p = __expf(d[j] - nm);
            sa[j] = sa[j] * c + p;
            a0[j] = a0[j] * c + p * v0[j];
            a1[j] = a1[j] * c + p * v1[j];
            m[j] = nm;
        }
    }
    float M0 = fmaxf(fmaxf(m[0], m[1]), fmaxf(m[2], m[3]));
    float S = 0.f, A0 = 0.f, A1 = 0.f;
#pragma unroll
    for (int j = 0; j < 4; j++) {
        float c = __expf(m[j] - M0);
        S += sa[j] * c;
        A0 += a0[j] * c;
        A1 += a1[j] * c;
    }
    if (lane == 0) { s_m[wid] = M0; s_s[wid] = S; }
    s_a[wid][lane * 2] = A0;
    s_a[wid][lane * 2 + 1] = A1;
    __syncthreads();
    if (wid == 0) {
        float MM = fmaxf(fmaxf(s_m[0], s_m[1]), fmaxf(s_m[2], s_m[3]));
        float c0 = __expf(s_m[0] - MM), c1 = __expf(s_m[1] - MM);
        float c2 = __expf(s_m[2] - MM), c3 = __expf(s_m[3] - MM);
        float SS = s_s[0] * c0 + s_s[1] * c1 + s_s[2] * c2 + s_s[3] * c3;
        float inv = 1.f / SS;
        int d0 = lane * 2;
        float r0 = (s_a[0][d0] * c0 + s_a[1][d0] * c1 + s_a[2][d0] * c2 + s_a[3][d0] * c3) * inv;
        int d1 = d0 + 1;
        float r1 = (s_a[0][d1] * c0 + s_a[1][d1] * c1 + s_a[2][d1] * c2 + s_a[3][d1] * c3) * inv;
        upd[(size_t)qi * DHEAD + d0] = r0;
        upd[(size_t)qi * DHEAD + d1] = r1;
    }
}

// ---------------- sel map ----------------
__global__ void selinit_kernel(int* __restrict__ sel) {
    int idx = blockIdx.x * blockDim.x + threadIdx.x;
    if (idx < BHCNT * LSEQ) sel[idx] = -1;
}
__global__ void selset_kernel(const int* __restrict__ Mtop, int* __restrict__ sel) {
    int idx = blockIdx.x * blockDim.x + threadIdx.x;
    if (idx >= BHCNT * UTOP) return;
    sel[(idx / UTOP) * LSEQ + Mtop[idx]] = idx % UTOP;
}

// ---------------- baseout: vmean-row @ wo + bo, per batch ----------------
__global__ void baseout_kernel(const float* __restrict__ vmean, const float* __restrict__ woT,
                               const float* __restrict__ bo, float* __restrict__ baseout) {
    __shared__ float vr[HID];
    int b = blockIdx.x;
    int n = threadIdx.x;  // 128
    vr[n] = vmean[b * HID + n];
    __syncthreads();
    float acc = bo[n];
    const float4* wrow = (const float4*)(woT + n * HID);
#pragma unroll
    for (int k4 = 0; k4 < 32; k4++) {
        float4 wv = wrow[k4];
        acc += vr[k4 * 4] * wv.x + vr[k4 * 4 + 1] * wv.y
             + vr[k4 * 4 + 2] * wv.z + vr[k4 * 4 + 3] * wv.w;
    }
    baseout[b * HID + n] = acc;
}

// ---------------- fill out with baseout ----------------
__global__ void fillout_kernel(const float* __restrict__ baseout, float* __restrict__ out) {
    int idx = blockIdx.x * blockDim.x + threadIdx.x;
    if (idx >= M2 * HID) return;
    int m = idx >> 7;
    int b = m / LSEQ;
    out[idx] = baseout[b * HID + (idx & 127)];
}

// ---------------- correction: recompute selected rows exactly ----------------
__global__ void __launch_bounds__(256)
correction_kernel(const int* __restrict__ Mtop, const int* __restrict__ sel,
                  const float* __restrict__ upd, const float* __restrict__ vmean,
                  const float* __restrict__ woT, const float* __restrict__ bo,
                  float* __restrict__ out) {
    __shared__ float rowv[8][HID];
    int wid = threadIdx.x >> 5;
    int lane = threadIdx.x & 31;
    int gw = blockIdx.x * 8 + wid;
    if (gw >= BHCNT * UTOP) return;
    int bh = gw / UTOP;
    int b = bh >> 1, h = bh & 1;
    int l = Mtop[gw];
    // if head 0 also selected this l, its warp covers the row; skip duplicate
    if (h == 1 && sel[(b * 2) * LSEQ + l] >= 0) return;
#pragma unroll
    for (int hh = 0; hh < 2; hh++) {
        int bhh = b * 2 + hh;
        int uu = sel[bhh * LSEQ + l];
        const float* src = (uu >= 0) ? (upd + ((size_t)bhh * UTOP + uu) * DHEAD)
                                     : (vmean + bhh * DHEAD);
        rowv[wid][hh * 64 + lane * 2]     = src[lane * 2];
        rowv[wid][hh * 64 + lane * 2 + 1] = src[lane * 2 + 1];
    }
    __syncwarp();
    float* orow = out + ((size_t)(b * LSEQ) + l) * HID;
#pragma unroll
    for (int jn = 0; jn < 4; jn++) {
        int n = lane * 4 + jn;
        float acc = bo[n];
        const float4* wrow = (const float4*)(woT + n * HID);
#pragma unroll
        for (int k4 = 0; k4 < 32; k4++) {
            float4 wv = wrow[k4];
            acc += rowv[wid][k4 * 4] * wv.x + rowv[wid][k4 * 4 + 1] * wv.y
                 + rowv[wid][k4 * 4 + 2] * wv.z + rowv[wid][k4 * 4 + 3] * wv.w;
        }
        orow[n] = acc;
    }
}

// ---------------- launch ----------------
extern "C" void kernel_launch(void* const* d_in, const int* in_sizes, int n_in,
                              void* d_out, int out_size) {
    const float* x       = (const float*)d_in[0];
    const float* conv1_w = (const float*)d_in[1];
    const float* conv1_b = (const float*)d_in[2];
    const float* conv2_w = (const float*)d_in[3];
    const float* conv2_b = (const float*)d_in[4];
    const float* wq = (const float*)d_in[5];
    const float* bq = (const float*)d_in[6];
    const float* wk = (const float*)d_in[7];
    const float* bk = (const float*)d_in[8];
    const float* wv = (const float*)d_in[9];
    const float* bv = (const float*)d_in[10];
    const float* wo = (const float*)d_in[11];
    const float* bo = (const float*)d_in[12];
    const int* index_sample = (const int*)d_in[13];
    float* out = (float*)d_out;

    float *xcl, *h1cl, *seq, *Qp, *Kp, *Vp, *Mv, *updv, *vmeanv;
    float *B1, *B2, *wqkvT, *woT, *baseout;
    int *mtop, *sel;
    cudaGetSymbolAddress((void**)&xcl, g_xcl);
    cudaGetSymbolAddress((void**)&h1cl, g_h1cl);
    cudaGetSymbolAddress((void**)&seq, g_seq);
    cudaGetSymbolAddress((void**)&Qp, g_Q);
    cudaGetSymbolAddress((void**)&Kp, g_K);
    cudaGetSymbolAddress((void**)&Vp, g_V);
    cudaGetSymbolAddress((void**)&Mv, g_M);
    cudaGetSymbolAddress((void**)&mtop, g_Mtop);
    cudaGetSymbolAddress((void**)&updv, g_upd);
    cudaGetSymbolAddress((void**)&vmeanv, g_vmean);
    cudaGetSymbolAddress((void**)&B1, g_B1);
    cudaGetSymbolAddress((void**)&B2, g_B2);
    cudaGetSymbolAddress((void**)&wqkvT, g_wqkvT);
    cudaGetSymbolAddress((void**)&woT, g_woT);
    cudaGetSymbolAddress((void**)&sel, g_sel);
    cudaGetSymbolAddress((void**)&baseout, g_baseout);

    cudaFuncSetAttribute((const void*)gemm_tc_kernel<1, K1, true, 1, 0>,
                         cudaFuncAttributeMaxDynamicSharedMemorySize, GEMM_SMEM_BYTES);
    cudaFuncSetAttribute((const void*)gemm_tc_kernel<2, K2, true, 1, 0>,
                         cudaFuncAttributeMaxDynamicSharedMemorySize, GEMM_SMEM_BYTES);
    cudaFuncSetAttribute((const void*)gemm_tc_kernel<0, HID, false, 3, 1>,
                         cudaFuncAttributeMaxDynamicSharedMemorySize, GEMM_SMEM_BYTES);

    // fused prep
    prep_kernel<<<(PREP_S4 + 255) / 256, 256>>>(x, conv1_w, conv2_w, wq, wk, wv, wo,
                                                xcl, B1, B2, wqkvT, woT);

    // conv1 -> h1cl (NHWC row-major), relu
    gemm_tc_kernel<1, K1, true, 1, 0>
        <<<(M1 + 127) / 128, 256, GEMM_SMEM_BYTES>>>(xcl, B1, conv1_b, conv1_b, conv1_b,
                                                     h1cl, h1cl, h1cl, M1);

    // conv2 -> seq, relu
    gemm_tc_kernel<2, K2, true, 1, 0>
        <<<(M2 + 127) / 128, 256, GEMM_SMEM_BYTES>>>(h1cl, B2, conv2_b, conv2_b, conv2_b,
                                                     seq, seq, seq, M2);

    // QKV: grid.y = 3, head layout
    gemm_tc_kernel<0, HID, false, 3, 1>
        <<<dim3((M2 + 127) / 128, 3), 256, GEMM_SMEM_BYTES>>>(seq, wqkvT, bq, bk, bv,
                                                              Qp, Kp, Vp, M2);

    // sampled scores -> M
    {
        int warps = BHCNT * LSEQ;
        sampled_m_kernel<<<(warps + 7) / 8, 256>>>(Qp, Kp, index_sample, Mv);
    }

    // top-40 (bitonic)
    topk_kernel<<<BHCNT, 256>>>(Mv, mtop);
    vmean_kernel<<<BHCNT, 256>>>(Vp, vmeanv);

    // sel map
    selinit_kernel<<<(BHCNT * LSEQ + 255) / 256, 256>>>(sel);
    selset_kernel<<<(BHCNT * UTOP + 255) / 256, 256>>>(mtop, sel);

    // attention (R8 per-query version)
    attn_kernel<<<BHCNT * UTOP, 128>>>(Qp, Kp, Vp, mtop, updv);

    // output: baseout broadcast + selected-row exact correction
    baseout_kernel<<<BATCH, HID>>>(vmeanv, woT, bo, baseout);
    fillout_kernel<<<(M2 * HID + 255) / 256, 256>>>(baseout, out);
    correction_kernel<<<(BHCNT * UTOP + 7) / 8, 256>>>(mtop, sel, updv, vmeanv,
                                                       woT, bo, out);
}

// round 13
// speedup vs baseline: 1.2043x; 1.1197x over previous
#include <cuda_runtime.h>
#include <cstdint>
#include <math.h>

#define NEG_INF (__int_as_float(0xff800000))

// ---------------- problem constants ----------------
#define BATCH   16
#define NFEAT   16
#define TLEN    64
#define SCL     32
#define HID     128
#define FS      4
#define NHEAD   2
#define DHEAD   64

#define H1H     61
#define H1W     29
#define H2H     58
#define H2W     26
#define LSEQ    1508
#define UTOP    40

#define K1      256
#define K2      2048
#define M1      (BATCH*H1H*H1W)   // 28304
#define M2      (BATCH*LSEQ)      // 24128
#define BHCNT   (BATCH*NHEAD)     // 32

#if defined(__CUDA_ARCH_FEAT_SM103_ALL) || defined(__CUDA_ARCH_SPECIFIC__)
#define TC_PATH 1
#else
#define TC_PATH 0
#endif

// ---------------- scratch ----------------
__device__ float g_xcl[BATCH*TLEN*SCL*NFEAT];
__device__ float g_h1cl[M1*HID];
__device__ float g_seq[M2*HID];
__device__ float g_Q[BHCNT*LSEQ*DHEAD];
__device__ float g_K[BHCNT*LSEQ*DHEAD];
__device__ float g_V[BHCNT*LSEQ*DHEAD];
__device__ float g_M[BHCNT*LSEQ];
__device__ int   g_Mtop[BHCNT*UTOP];
__device__ float g_upd[BHCNT*UTOP*DHEAD];
__device__ float g_vmean[BHCNT*DHEAD];
__device__ float g_B1[HID*K1];
__device__ float g_B2[HID*K2];
__device__ float g_wqkvT[3*HID*HID];
__device__ float g_woT[HID*HID];
__device__ int   g_sel[BHCNT*LSEQ];

// ---------------- PTX helpers ----------------
__device__ __forceinline__ uint32_t smem_u32(const void* p) {
    uint32_t a;
    asm("{ .reg .u64 t; cvta.to.shared.u64 t, %1; cvt.u32.u64 %0, t; }" : "=r"(a) : "l"(p));
    return a;
}

#define TC_ALLOC(sa, n) \
    asm volatile("tcgen05.alloc.cta_group::1.sync.aligned.shared::cta.b32 [%0], %1;" \
                 :: "r"(sa), "r"(n) : "memory")
#define TC_DEALLOC(t, n) \
    asm volatile("tcgen05.dealloc.cta_group::1.sync.aligned.b32 %0, %1;" :: "r"(t), "r"(n))
#define TC_RELINQ() \
    asm volatile("tcgen05.relinquish_alloc_permit.cta_group::1.sync.aligned;")
#define TC_COMMIT(mb) \
    asm volatile("tcgen05.commit.cta_group::1.mbarrier::arrive::one.shared::cluster.b64 [%0];" \
                 :: "r"(mb) : "memory")
#define TC_FENCE_AFTER()  asm volatile("tcgen05.fence::after_thread_sync;" ::: "memory")
#define TC_FENCE_BEFORE() asm volatile("tcgen05.fence::before_thread_sync;" ::: "memory")
#define TC_WAIT_LD()      asm volatile("tcgen05.wait::ld.sync.aligned;" ::: "memory")
#define MB_INIT(mb, c) \
    asm volatile("mbarrier.init.shared.b64 [%0], %1;" :: "r"(mb), "r"(c) : "memory")
#define FENCE_ASYNC() asm volatile("fence.proxy.async.shared::cta;" ::: "memory")

#define MB_WAIT_PARITY(mbar_smem_addr, phase_parity) do { \
    uint32_t _mbar = (uint32_t)(mbar_smem_addr); \
    uint32_t _parity = (uint32_t)(phase_parity); \
    uint32_t _done; \
    asm volatile( \
        "{\n\t" \
        ".reg .pred p;\n\t" \
        "mbarrier.try_wait.parity.acquire.cta.shared::cta.b64 p, [%1], %2;\n\t" \
        "selp.b32 %0, 1, 0, p;\n\t" \
        "}" \
        : "=r"(_done) : "r"(_mbar), "r"(_parity) : "memory"); \
    if (!_done) { \
        asm volatile( \
            "{\n\t" \
            ".reg .pred P1;\n\t" \
            "WAIT_LOOP_%=:\n\t" \
            "mbarrier.try_wait.parity.acquire.cta.shared::cta.b64 P1, [%0], %1, 0x989680;\n\t" \
            "@P1 bra.uni WAIT_DONE_%=;\n\t" \
            "bra.uni WAIT_LOOP_%=;\n\t" \
            "WAIT_DONE_%=:\n\t" \
            "}" \
            :: "r"(_mbar), "r"(_parity) : "memory"); \
    } \
} while(0)

#define TC_LD_X32(r, tmem_addr) \
    asm volatile( \
        "tcgen05.ld.sync.aligned.32x32b.x32.b32 " \
        "{%0, %1, %2, %3, %4, %5, %6, %7, " \
        " %8, %9, %10, %11, %12, %13, %14, %15, " \
        " %16, %17, %18, %19, %20, %21, %22, %23, " \
        " %24, %25, %26, %27, %28, %29, %30, %31}, [%32];" \
        : "=r"((r)[0]),  "=r"((r)[1]),  "=r"((r)[2]),  "=r"((r)[3]), \
          "=r"((r)[4]),  "=r"((r)[5]),  "=r"((r)[6]),  "=r"((r)[7]), \
          "=r"((r)[8]),  "=r"((r)[9]),  "=r"((r)[10]), "=r"((r)[11]), \
          "=r"((r)[12]), "=r"((r)[13]), "=r"((r)[14]), "=r"((r)[15]), \
          "=r"((r)[16]), "=r"((r)[17]), "=r"((r)[18]), "=r"((r)[19]), \
          "=r"((r)[20]), "=r"((r)[21]), "=r"((r)[22]), "=r"((r)[23]), \
          "=r"((r)[24]), "=r"((r)[25]), "=r"((r)[26]), "=r"((r)[27]), \
          "=r"((r)[28]), "=r"((r)[29]), "=r"((r)[30]), "=r"((r)[31]) \
        : "r"(tmem_addr))

#if TC_PATH
__device__ __forceinline__ void mma_tf32_ss(uint32_t d_tmem, uint64_t a_desc,
                                            uint64_t b_desc, uint32_t idesc, bool accum) {
    uint32_t en = accum ? 1u : 0u;
    asm volatile(
        "{\n\t"
        ".reg .pred p;\n\t"
        "setp.ne.u32 p, %4, 0;\n\t"
        "tcgen05.mma.cta_group::1.kind::tf32 [%0], %1, %2, %3, p;\n\t"
        "}"
        :: "r"(d_tmem), "l"(a_desc), "l"(b_desc), "r"(idesc), "r"(en)
        : "memory");
}
#endif

__device__ __forceinline__ uint64_t make_desc(uint32_t addr) {
    return ((uint64_t)2 << 61) | ((uint64_t)1 << 46) | ((uint64_t)64 << 32)
         | ((uint64_t)1 << 16) | (uint64_t)((addr >> 4) & 0x3FFF);
}

__device__ __forceinline__ uint32_t swz128(uint32_t off) {
    return off ^ ((off >> 3) & 0x70);
}

__device__ __forceinline__ void split_tf32(float v, float& hi, float& lo) {
    uint32_t h;
    asm("cvt.rna.tf32.f32 %0, %1;" : "=r"(h) : "f"(v));
    hi = __uint_as_float(h);
    lo = v - hi;
}

#define TF32_IDESC ((1u << 4) | (2u << 7) | (2u << 10) | (16u << 17) | (8u << 24))

// ---------------- fused prep kernel ----------------
#define PREP_S0 (BATCH*NFEAT*TLEN*SCL)
#define PREP_S1 (PREP_S0 + HID*K1)
#define PREP_S2 (PREP_S1 + HID*K2)
#define PREP_S3 (PREP_S2 + 3*HID*HID)
#define PREP_S4 (PREP_S3 + HID*HID)
__global__ void prep_kernel(const float* __restrict__ x,
                            const float* __restrict__ c1w, const float* __restrict__ c2w,
                            const float* __restrict__ wq, const float* __restrict__ wk,
                            const float* __restrict__ wv, const float* __restrict__ wo,
                            float* __restrict__ xcl, float* __restrict__ B1,
                            float* __restrict__ B2, float* __restrict__ wqkvT,
                            float* __restrict__ woT) {
    int idx = blockIdx.x * blockDim.x + threadIdx.x;
    if (idx < PREP_S0) {
        int w = idx % SCL;
        int h = (idx / SCL) % TLEN;
        int c = (idx / (SCL * TLEN)) % NFEAT;
        int b = idx / (SCL * TLEN * NFEAT);
        xcl[((b * TLEN + h) * SCL + w) * NFEAT + c] = x[idx];
    } else if (idx < PREP_S1) {
        int i = idx - PREP_S0;
        int n = i / K1, k = i % K1;
        int ic = k / 16, s = k % 16;
        B1[n * K1 + s * NFEAT + ic] = c1w[i];
    } else if (idx < PREP_S2) {
        int i = idx - PREP_S1;
        int n = i / K2, k = i % K2;
        int ic = k / 16, s = k % 16;
        B2[n * K2 + s * HID + ic] = c2w[i];
    } else if (idx < PREP_S3) {
        int i = idx - PREP_S2;
        int mat = i / (HID * HID);
        int r = i % (HID * HID);
        int a = r / HID, b = r % HID;
        const float* w = (mat == 0) ? wq : (mat == 1) ? wk : wv;
        wqkvT[mat * HID * HID + b * HID + a] = w[r];
    } else if (idx < PREP_S4) {
        int i = idx - PREP_S3;
        int a = i / HID, b = i % HID;
        woT[b * HID + a] = wo[i];
    }
}

// ---------------- tcgen05 3xTF32 GEMM (R8 config, locked) ----------------
// MODE 0: A row-major. MODE 1: conv1 im2col. MODE 2: conv2 im2col.
// MODE 3: A gathered from (upd|vmean) via sel map (fused ctx for final proj).
#define GEMM_SMEM_BYTES (79872)

template<int MODE, int KDIM, bool RELU, int NMAT, int LAYOUT>
__global__ void __launch_bounds__(256, 2)
gemm_tc_kernel(const float* __restrict__ Ain, const float* __restrict__ BwAll,
               const float* __restrict__ b0, const float* __restrict__ b1p,
               const float* __restrict__ b2p,
               float* __restrict__ o0, float* __restrict__ o1p, float* __restrict__ o2p,
               int M,
               const int* __restrict__ sel, const float* __restrict__ updp,
               const float* __restrict__ vmeanp) {
    const int mat = (NMAT > 1) ? blockIdx.y : 0;
    const float* Bw = BwAll + (size_t)mat * HID * KDIM;
    const float* bias = (mat == 0) ? b0 : (mat == 1) ? b1p : b2p;
    float* out = (mat == 0) ? o0 : (mat == 1) ? o1p : o2p;

#if TC_PATH
    extern __shared__ char dynraw[];
    __shared__ uint32_t s_tmem[1];
    __shared__ __align__(8) unsigned long long s_mbar[1];

    const int tid = threadIdx.x;
    const int wid = tid >> 5;
    const int lane = tid & 31;
    const int block_m = blockIdx.x * 128;

    uint32_t dynb32 = smem_u32(dynraw);
    uint32_t smem_base = (dynb32 + 1023u) & ~1023u;
    char* dbase = dynraw + (smem_base - dynb32);
    uint32_t mbar0 = smem_u32(&s_mbar[0]);

    if (wid == 0) {
        TC_ALLOC(smem_u32(s_tmem), 256);
        TC_RELINQ();
    }
    if (tid == 0) MB_INIT(mbar0, 1);
    __syncthreads();
    uint32_t tmem;
    asm volatile("ld.shared.b32 %0, [%1];" : "=r"(tmem) : "r"(smem_u32(s_tmem)));

    const int quad = tid & 7;
    int rowi[4], abase[4], bh2[4];
    bool aok[4];
#pragma unroll
    for (int i = 0; i < 4; i++) {
        rowi[i] = i * 32 + (tid >> 3);
        int m = block_m + rowi[i];
        aok[i] = (m < M);
        int mc = aok[i] ? m : 0;
        bh2[i] = 0;
        if (MODE == 0) {
            abase[i] = mc * KDIM;
        } else if (MODE == 1) {
            int b = mc / (H1H * H1W);
            int r = mc % (H1H * H1W);
            abase[i] = ((b * TLEN + r / H1W) * SCL + (r % H1W)) * NFEAT;
        } else if (MODE == 2) {
            int b = mc / LSEQ;
            int r = mc % LSEQ;
            abase[i] = ((b * H1H + r / H2W) * H1W + (r % H2W)) * HID;
        } else {   // MODE 3: sel-gathered ctx
            int b = mc / LSEQ;
            int l = mc % LSEQ;
            abase[i] = b * NHEAD * LSEQ + l;   // sel base; + h*LSEQ
            bh2[i] = b * NHEAD;
        }
    }
    uint32_t swz[4];
#pragma unroll
    for (int i = 0; i < 4; i++)
        swz[i] = swz128((uint32_t)rowi[i] * 128u + (uint32_t)quad * 16u);

    float4 areg[4], breg[4];
    auto load_regs = [&](int c) {
        const int kq = c * 32 + quad * 4;
#pragma unroll
        for (int i = 0; i < 4; i++) {
            areg[i] = make_float4(0.f, 0.f, 0.f, 0.f);
            if (aok[i]) {
                if (MODE == 3) {
                    int h = kq >> 6, d = kq & 63;
                    int u = __ldg(&sel[abase[i] + h * LSEQ]);
                    int bh = bh2[i] + h;
                    const float* src = (u >= 0)
                        ? updp + ((size_t)bh * UTOP + u) * DHEAD + d
                        : vmeanp + bh * DHEAD + d;
                    areg[i] = *reinterpret_cast<const float4*>(src);
                } else {
                    int addr;
                    if (MODE == 0) {
                        addr = abase[i] + kq;
                    } else if (MODE == 1) {
                        int s = kq >> 4, ic = kq & 15;
                        addr = abase[i] + (((s >> 2) * SCL) + (s & 3)) * NFEAT + ic;
                    } else {
                        int s = kq >> 7, ic = kq & 127;
                        addr = abase[i] + (((s >> 2) * H1W) + (s & 3)) * HID + ic;
                    }
                    areg[i] = *reinterpret_cast<const float4*>(Ain + addr);
                }
            }
            breg[i] = *reinterpret_cast<const float4*>(Bw + rowi[i] * KDIM + kq);
        }
    };
    auto store_tiles = [&]() {
        char* Ahi = dbase;
        char* Alo = Ahi + 16384;
        char* Bhi = Ahi + 32768;
        char* Blo = Ahi + 49152;
#pragma unroll
        for (int i = 0; i < 4; i++) {
            float4 h4, l4;
            split_tf32(areg[i].x, h4.x, l4.x);
            split_tf32(areg[i].y, h4.y, l4.y);
            split_tf32(areg[i].z, h4.z, l4.z);
            split_tf32(areg[i].w, h4.w, l4.w);
            *reinterpret_cast<float4*>(Ahi + swz[i]) = h4;
            *reinterpret_cast<float4*>(Alo + swz[i]) = l4;
            split_tf32(breg[i].x, h4.x, l4.x);
            split_tf32(breg[i].y, h4.y, l4.y);
            split_tf32(breg[i].z, h4.z, l4.z);
            split_tf32(breg[i].w, h4.w, l4.w);
            *reinterpret_cast<float4*>(Bhi + swz[i]) = h4;
            *reinterpret_cast<float4*>(Blo + swz[i]) = l4;
        }
    };

    const int NC = KDIM / 32;
    int ph = 0;
    load_regs(0);

    for (int c = 0; c < NC; c++) {
        if (c > 0) {
            MB_WAIT_PARITY(mbar0, ph);
            ph ^= 1;
        }
        store_tiles();
        if (c + 1 < NC) load_regs(c + 1);
        FENCE_ASYNC();
        __syncthreads();
        if (tid == 0) {
            uint64_t dah = make_desc(smem_base);
            uint64_t dal = make_desc(smem_base + 16384);
            uint64_t dbh = make_desc(smem_base + 32768);
            uint64_t dbl = make_desc(smem_base + 49152);
#pragma unroll
            for (int s = 0; s < 4; s++) {
                uint64_t o = (uint64_t)(s * 2);
                mma_tf32_ss(tmem, dah + o, dbh + o, TF32_IDESC, !(c == 0 && s == 0));
                mma_tf32_ss(tmem, dah + o, dbl + o, TF32_IDESC, true);
                mma_tf32_ss(tmem, dal + o, dbh + o, TF32_IDESC, true);
            }
            TC_COMMIT(mbar0);
        }
    }
    MB_WAIT_PARITY(mbar0, ph);
    TC_FENCE_AFTER();
    __syncthreads();

    if (wid < 4) {
        int m = block_m + wid * 32 + lane;
#pragma unroll
        for (int cb = 0; cb < 128; cb += 32) {
            uint32_t r[32];
            TC_LD_X32(r, tmem + cb);
            TC_WAIT_LD();
            if (m < M) {
                float vals[32];
#pragma unroll
                for (int j = 0; j < 32; j++) {
                    float v = __uint_as_float(r[j]) + __ldg(&bias[cb + j]);
                    if (RELU) v = fmaxf(v, 0.f);
                    vals[j] = v;
                }
                float* po;
                if (LAYOUT == 0) {
                    po = out + (size_t)m * HID + cb;
                } else {
                    int b = m / LSEQ, l = m % LSEQ;
                    int h = cb >> 6, d0 = cb & 63;
                    po = out + ((size_t)(b * NHEAD + h) * LSEQ + l) * DHEAD + d0;
                }
#pragma unroll
                for (int j = 0; j < 8; j++) {
                    *reinterpret_cast<float4*>(po + j * 4) =
                        make_float4(vals[j * 4], vals[j * 4 + 1], vals[j * 4 + 2], vals[j * 4 + 3]);
                }
            }
        }
        TC_FENCE_BEFORE();
    }
    __syncthreads();
    if (wid == 0) TC_DEALLOC(tmem, 256);
#else
    // naive fallback (family PTX pass; exact sm_103a cubin preferred on GB300)
    const int tid = threadIdx.x;
    const int block_m = blockIdx.x * 128;
    for (int e = tid; e < 128 * 128; e += 256) {
        int mi = e >> 7, n = e & 127;
        int m = block_m + mi;
        if (m >= M) continue;
        float acc = 0.f;
        for (int k = 0; k < KDIM; k++) {
            float a;
            if (MODE == 0) {
                a = Ain[(size_t)m * KDIM + k];
            } else if (MODE == 1) {
                int b = m / (H1H * H1W), r = m % (H1H * H1W);
                int s = k >> 4, ic = k & 15;
                a = Ain[((b * TLEN + r / H1W + (s >> 2)) * SCL + (r % H1W) + (s & 3)) * NFEAT + ic];
            } else if (MODE == 2) {
                int b = m / LSEQ, r = m % LSEQ;
                int s = k >> 7, ic = k & 127;
                a = Ain[((b * H1H + r / H2W + (s >> 2)) * H1W + (r % H2W) + (s & 3)) * HID + ic];
            } else {
                int b = m / LSEQ, l = m % LSEQ;
                int h = k >> 6, d = k & 63;
                int u = sel[(b * NHEAD + h) * LSEQ + l];
                int bh = b * NHEAD + h;
                a = (u >= 0) ? updp[((size_t)bh * UTOP + u) * DHEAD + d]
                             : vmeanp[bh * DHEAD + d];
            }
            acc += a * Bw[n * KDIM + k];
        }
        acc += bias[n];
        if (RELU) acc = fmaxf(acc, 0.f);
        if (LAYOUT == 0) {
            out[(size_t)m * HID + n] = acc;
        } else {
            int b = m / LSEQ, l = m % LSEQ;
            int h = n >> 6, d = n & 63;
            out[((size_t)(b * NHEAD + h) * LSEQ + l) * DHEAD + d] = acc;
        }
    }
#endif
}

// ---------------- helpers ----------------
__device__ __forceinline__ float warp_sum(float v) {
    v += __shfl_xor_sync(0xffffffffu, v, 16);
    v += __shfl_xor_sync(0xffffffffu, v, 8);
    v += __shfl_xor_sync(0xffffffffu, v, 4);
    v += __shfl_xor_sync(0xffffffffu, v, 2);
    v += __shfl_xor_sync(0xffffffffu, v, 1);
    return v;
}

// ---------------- sampled scores -> M ----------------
__global__ void sampled_m_kernel(const float* __restrict__ Q, const float* __restrict__ K,
                                 const int* __restrict__ idxs, float* __restrict__ Mout) {
    int gwarp = (blockIdx.x * blockDim.x + threadIdx.x) >> 5;
    int lane = threadIdx.x & 31;
    if (gwarp >= BHCNT * LSEQ) return;
    int bh = gwarp / LSEQ;
    int l  = gwarp % LSEQ;
    const float* q = Q + (size_t)gwarp * DHEAD;
    float q0 = q[lane * 2], q1 = q[lane * 2 + 1];
    const float* Kb = K + (size_t)bh * LSEQ * DHEAD;
    float mx = NEG_INF, sm = 0.f;
#pragma unroll 1
    for (int u = 0; u < UTOP; u += 8) {
        float d[8];
#pragma unroll
        for (int j = 0; j < 8; j++) {
            int ki = __ldg(&idxs[l * UTOP + u + j]);
            const float* kr = Kb + (size_t)ki * DHEAD;
            d[j] = q0 * kr[lane * 2] + q1 * kr[lane * 2 + 1];
        }
#pragma unroll
        for (int j = 0; j < 8; j++) d[j] = warp_sum(d[j]);
#pragma unroll
        for (int j = 0; j < 8; j++) { mx = fmaxf(mx, d[j]); sm += d[j]; }
    }
    if (lane == 0) Mout[gwarp] = mx - sm / (float)LSEQ;
}

// ---------------- top-40 via bitonic sort of 2048 keys ----------------
#define SORTN 2048
__global__ void __launch_bounds__(256)
topk_kernel(const float* __restrict__ Min, int* __restrict__ Mtop) {
    __shared__ unsigned long long keys[SORTN];
    int bh = blockIdx.x;
    int tid = threadIdx.x;
    for (int j = tid; j < SORTN; j += 256) {
        unsigned long long key;
        if (j < LSEQ) {
            uint32_t b = __float_as_uint(Min[bh * LSEQ + j]);
            uint32_t s = (b & 0x80000000u) ? ~b : (b | 0x80000000u);
            key = ((unsigned long long)(~s) << 32) | (uint32_t)j;
        } else {
            key = 0xFFFFFFFFFFFFFFFFull;
        }
        keys[j] = key;
    }
    __syncthreads();
    for (int k = 2; k <= SORTN; k <<= 1) {
        for (int j = k >> 1; j > 0; j >>= 1) {
#pragma unroll 4
            for (int t = tid; t < SORTN / 2; t += 256) {
                int i = ((t / j) * j * 2) + (t % j);
                int l2 = i + j;
                bool up = ((i & k) == 0);
                unsigned long long a = keys[i], b = keys[l2];
                if ((a > b) == up) { keys[i] = b; keys[l2] = a; }
            }
            __syncthreads();
        }
    }
    if (tid < UTOP)
        Mtop[bh * UTOP + tid] = (int)(keys[tid] & 0xFFFFFFFFull);
}

// ---------------- V mean per (b,h) ----------------
#define VSLICE 377    // LSEQ/4
__global__ void vmean_kernel(const float* __restrict__ V, float* __restrict__ vmean) {
    __shared__ float part[4][DHEAD];
    int bh = blockIdx.x;
    int tid = threadIdx.x;
    int d = tid & 63;
    int sl = tid >> 6;
    const float* Vb = V + (size_t)bh * LSEQ * DHEAD;
    float s = 0.f;
    int beg = sl * VSLICE, end = beg + VSLICE;
    for (int l = beg; l < end; l++) s += Vb[(size_t)l * DHEAD + d];
    part[sl][d] = s;
    __syncthreads();
    if (tid < DHEAD)
        vmean[bh * DHEAD + tid] =
            (part[0][tid] + part[1][tid] + part[2][tid] + part[3][tid]) / (float)LSEQ;
}

// ---------------- attention: 1 block (4 warps) per selected query ----------------
__global__ void attn_kernel(const float* __restrict__ Q, const float* __restrict__ K,
                            const float* __restrict__ V, const int* __restrict__ Mtop,
                            float* __restrict__ upd) {
    __shared__ float s_m[4], s_s[4], s_a[4][DHEAD];
    int qi = blockIdx.x;
    int bh = qi / UTOP;
    int l = Mtop[qi];
    int wid = threadIdx.x >> 5;
    int lane = threadIdx.x & 31;
    const float* q = Q + ((size_t)bh * LSEQ + l) * DHEAD;
    float q0 = q[lane * 2], q1 = q[lane * 2 + 1];
    const float* Kb = K + (size_t)bh * LSEQ * DHEAD;
    const float* Vb = V + (size_t)bh * LSEQ * DHEAD;

    int beg = wid * VSLICE, end = beg + VSLICE;
    float m[4], sa[4], a0[4], a1[4];
#pragma unroll
    for (int j = 0; j < 4; j++) { m[j] = NEG_INF; sa[j] = 0.f; a0[j] = 0.f; a1[j] = 0.f; }

#pragma unroll 1
    for (int k0 = beg; k0 < end; k0 += 4) {
        float d[4], v0[4], v1[4];
#pragma unroll
        for (int j = 0; j < 4; j++) {
            int kk = (k0 + j < end) ? (k0 + j) : beg;
            const float* kr = Kb + (size_t)kk * DHEAD;
            d[j] = q0 * kr[lane * 2] + q1 * kr[lane * 2 + 1];
        }
#pragma unroll
        for (int j = 0; j < 4; j++) d[j] = warp_sum(d[j]) * 0.125f;
#pragma unroll
        for (int j = 0; j < 4; j++) {
            int kk = (k0 + j < end) ? (k0 + j) : beg;
            const float* vr = Vb + (size_t)kk * DHEAD;
            v0[j] = vr[lane * 2];
            v1[j] = vr[lane * 2 + 1];
        }
#pragma unroll
        for (int j = 0; j < 4; j++) {
            if (k0 + j >= end) continue;
            float nm = fmaxf(m[j], d[j]);
            float c = __expf(m[j] - nm);
            float p = __expf(d[j] - nm);
            sa[j] = sa[j] * c + p;
            a0[j] = a0[j] * c + p * v0[j];
            a1[j] = a1[j] * c + p * v1[j];
            m[j] = nm;
        }
    }
    float M0 = fmaxf(fmaxf(m[0], m[1]), fmaxf(m[2], m[3]));
    float S = 0.f, A0 = 0.f, A1 = 0.f;
#pragma unroll
    for (int j = 0; j < 4; j++) {
        float c = __expf(m[j] - M0);
        S += sa[j] * c;
        A0 += a0[j] * c;
        A1 += a1[j] * c;
    }
    if (lane == 0) { s_m[wid] = M0; s_s[wid] = S; }
    s_a[wid][lane * 2] = A0;
    s_a[wid][lane * 2 + 1] = A1;
    __syncthreads();
    if (wid == 0) {
        float MM = fmaxf(fmaxf(s_m[0], s_m[1]), fmaxf(s_m[2], s_m[3]));
        float c0 = __expf(s_m[0] - MM), c1 = __expf(s_m[1] - MM);
        float c2 = __expf(s_m[2] - MM), c3 = __expf(s_m[3] - MM);
        float SS = s_s[0] * c0 + s_s[1] * c1 + s_s[2] * c2 + s_s[3] * c3;
        float inv = 1.f / SS;
        int d0 = lane * 2;
        float r0 = (s_a[0][d0] * c0 + s_a[1][d0] * c1 + s_a[2][d0] * c2 + s_a[3][d0] * c3) * inv;
        int d1 = d0 + 1;
        float r1 = (s_a[0][d1] * c0 + s_a[1][d1] * c1 + s_a[2][d1] * c2 + s_a[3][d1] * c3) * inv;
        upd[(size_t)qi * DHEAD + d0] = r0;
        upd[(size_t)qi * DHEAD + d1] = r1;
    }
}

// ---------------- sel map ----------------
__global__ void selinit_kernel(int* __restrict__ sel) {
    int idx = blockIdx.x * blockDim.x + threadIdx.x;
    if (idx < BHCNT * LSEQ) sel[idx] = -1;
}
__global__ void selset_kernel(const int* __restrict__ Mtop, int* __restrict__ sel) {
    int idx = blockIdx.x * blockDim.x + threadIdx.x;
    if (idx >= BHCNT * UTOP) return;
    sel[(idx / UTOP) * LSEQ + Mtop[idx]] = idx % UTOP;
}

// ---------------- launch ----------------
extern "C" void kernel_launch(void* const* d_in, const int* in_sizes, int n_in,
                              void* d_out, int out_size) {
    const float* x       = (const float*)d_in[0];
    const float* conv1_w = (const float*)d_in[1];
    const float* conv1_b = (const float*)d_in[2];
    const float* conv2_w = (const float*)d_in[3];
    const float* conv2_b = (const float*)d_in[4];
    const float* wq = (const float*)d_in[5];
    const float* bq = (const float*)d_in[6];
    const float* wk = (const float*)d_in[7];
    const float* bk = (const float*)d_in[8];
    const float* wv = (const float*)d_in[9];
    const float* bv = (const float*)d_in[10];
    const float* wo = (const float*)d_in[11];
    const float* bo = (const float*)d_in[12];
    const int* index_sample = (const int*)d_in[13];
    float* out = (float*)d_out;

    float *xcl, *h1cl, *seq, *Qp, *Kp, *Vp, *Mv, *updv, *vmeanv;
    float *B1, *B2, *wqkvT, *woT;
    int *mtop, *sel;
    cudaGetSymbolAddress((void**)&xcl, g_xcl);
    cudaGetSymbolAddress((void**)&h1cl, g_h1cl);
    cudaGetSymbolAddress((void**)&seq, g_seq);
    cudaGetSymbolAddress((void**)&Qp, g_Q);
    cudaGetSymbolAddress((void**)&Kp, g_K);
    cudaGetSymbolAddress((void**)&Vp, g_V);
    cudaGetSymbolAddress((void**)&Mv, g_M);
    cudaGetSymbolAddress((void**)&mtop, g_Mtop);
    cudaGetSymbolAddress((void**)&updv, g_upd);
    cudaGetSymbolAddress((void**)&vmeanv, g_vmean);
    cudaGetSymbolAddress((void**)&B1, g_B1);
    cudaGetSymbolAddress((void**)&B2, g_B2);
    cudaGetSymbolAddress((void**)&wqkvT, g_wqkvT);
    cudaGetSymbolAddress((void**)&woT, g_woT);
    cudaGetSymbolAddress((void**)&sel, g_sel);

    cudaFuncSetAttribute((const void*)gemm_tc_kernel<1, K1, true, 1, 0>,
                         cudaFuncAttributeMaxDynamicSharedMemorySize, GEMM_SMEM_BYTES);
    cudaFuncSetAttribute((const void*)gemm_tc_kernel<2, K2, true, 1, 0>,
                         cudaFuncAttributeMaxDynamicSharedMemorySize, GEMM_SMEM_BYTES);
    cudaFuncSetAttribute((const void*)gemm_tc_kernel<0, HID, false, 3, 1>,
                         cudaFuncAttributeMaxDynamicSharedMemorySize, GEMM_SMEM_BYTES);
    cudaFuncSetAttribute((const void*)gemm_tc_kernel<3, HID, false, 1, 0>,
                         cudaFuncAttributeMaxDynamicSharedMemorySize, GEMM_SMEM_BYTES);

    // fused prep
    prep_kernel<<<(PREP_S4 + 255) / 256, 256>>>(x, conv1_w, conv2_w, wq, wk, wv, wo,
                                                xcl, B1, B2, wqkvT, woT);

    // conv1 -> h1cl (NHWC row-major), relu
    gemm_tc_kernel<1, K1, true, 1, 0>
        <<<(M1 + 127) / 128, 256, GEMM_SMEM_BYTES>>>(xcl, B1, conv1_b, conv1_b, conv1_b,
                                                     h1cl, h1cl, h1cl, M1,
                                                     nullptr, nullptr, nullptr);

    // conv2 -> seq, relu
    gemm_tc_kernel<2, K2, true, 1, 0>
        <<<(M2 + 127) / 128, 256, GEMM_SMEM_BYTES>>>(h1cl, B2, conv2_b, conv2_b, conv2_b,
                                                     seq, seq, seq, M2,
                                                     nullptr, nullptr, nullptr);

    // QKV: grid.y = 3, head layout
    gemm_tc_kernel<0, HID, false, 3, 1>
        <<<dim3((M2 + 127) / 128, 3), 256, GEMM_SMEM_BYTES>>>(seq, wqkvT, bq, bk, bv,
                                                              Qp, Kp, Vp, M2,
                                                              nullptr, nullptr, nullptr);

    // sampled scores -> M
    {
        int warps = BHCNT * LSEQ;
        sampled_m_kernel<<<(warps + 7) / 8, 256>>>(Qp, Kp, index_sample, Mv);
    }

    // top-40 (bitonic) + vmean
    topk_kernel<<<BHCNT, 256>>>(Mv, mtop);
    vmean_kernel<<<BHCNT, 256>>>(Vp, vmeanv);

    // sel map
    selinit_kernel<<<(BHCNT * LSEQ + 255) / 256, 256>>>(sel);
    selset_kernel<<<(BHCNT * UTOP + 255) / 256, 256>>>(mtop, sel);

    // attention (R8 per-query version)
    attn_kernel<<<BHCNT * UTOP, 128>>>(Qp, Kp, Vp, mtop, updv);

    // final projection with fused ctx gather (MODE 3)
    gemm_tc_kernel<3, HID, false, 1, 0>
        <<<(M2 + 127) / 128, 256, GEMM_SMEM_BYTES>>>(nullptr, woT, bo, bo, bo,
                                                     out, out, out, M2,
                                                     sel, updv, vmeanv);
}

// round 14
// speedup vs baseline: 1.2334x; 1.0241x over previous
#include <cuda_runtime.h>
#include <cstdint>
#include <math.h>

#define NEG_INF (__int_as_float(0xff800000))

// ---------------- problem constants ----------------
#define BATCH   16
#define NFEAT   16
#define TLEN    64
#define SCL     32
#define HID     128
#define FS      4
#define NHEAD   2
#define DHEAD   64

#define H1H     61
#define H1W     29
#define H2H     58
#define H2W     26
#define LSEQ    1508
#define UTOP    40

#define K1      256
#define K2      2048
#define M1      (BATCH*H1H*H1W)   // 28304
#define M2      (BATCH*LSEQ)      // 24128
#define BHCNT   (BATCH*NHEAD)     // 32

#if defined(__CUDA_ARCH_FEAT_SM103_ALL) || defined(__CUDA_ARCH_SPECIFIC__)
#define TC_PATH 1
#else
#define TC_PATH 0
#endif

// ---------------- scratch ----------------
__device__ float g_xcl[BATCH*TLEN*SCL*NFEAT];
__device__ float g_h1cl[M1*HID];
__device__ float g_seq[M2*HID];
__device__ float g_part[2*M2*HID];
__device__ float g_Q[BHCNT*LSEQ*DHEAD];
__device__ float g_K[BHCNT*LSEQ*DHEAD];
__device__ float g_V[BHCNT*LSEQ*DHEAD];
__device__ float g_M[BHCNT*LSEQ];
__device__ int   g_Mtop[BHCNT*UTOP];
__device__ float g_upd[BHCNT*UTOP*DHEAD];
__device__ float g_vmean[BHCNT*DHEAD];
__device__ float g_B1[HID*K1];
__device__ float g_B2[HID*K2];
__device__ float g_wqkvT[3*HID*HID];
__device__ float g_woT[HID*HID];
__device__ int   g_sel[BHCNT*LSEQ];

// ---------------- PTX helpers ----------------
__device__ __forceinline__ uint32_t smem_u32(const void* p) {
    uint32_t a;
    asm("{ .reg .u64 t; cvta.to.shared.u64 t, %1; cvt.u32.u64 %0, t; }" : "=r"(a) : "l"(p));
    return a;
}

#define TC_ALLOC(sa, n) \
    asm volatile("tcgen05.alloc.cta_group::1.sync.aligned.shared::cta.b32 [%0], %1;" \
                 :: "r"(sa), "r"(n) : "memory")
#define TC_DEALLOC(t, n) \
    asm volatile("tcgen05.dealloc.cta_group::1.sync.aligned.b32 %0, %1;" :: "r"(t), "r"(n))
#define TC_RELINQ() \
    asm volatile("tcgen05.relinquish_alloc_permit.cta_group::1.sync.aligned;")
#define TC_COMMIT(mb) \
    asm volatile("tcgen05.commit.cta_group::1.mbarrier::arrive::one.shared::cluster.b64 [%0];" \
                 :: "r"(mb) : "memory")
#define TC_FENCE_AFTER()  asm volatile("tcgen05.fence::after_thread_sync;" ::: "memory")
#define TC_FENCE_BEFORE() asm volatile("tcgen05.fence::before_thread_sync;" ::: "memory")
#define TC_WAIT_LD()      asm volatile("tcgen05.wait::ld.sync.aligned;" ::: "memory")
#define MB_INIT(mb, c) \
    asm volatile("mbarrier.init.shared.b64 [%0], %1;" :: "r"(mb), "r"(c) : "memory")
#define FENCE_ASYNC() asm volatile("fence.proxy.async.shared::cta;" ::: "memory")

#define MB_WAIT_PARITY(mbar_smem_addr, phase_parity) do { \
    uint32_t _mbar = (uint32_t)(mbar_smem_addr); \
    uint32_t _parity = (uint32_t)(phase_parity); \
    uint32_t _done; \
    asm volatile( \
        "{\n\t" \
        ".reg .pred p;\n\t" \
        "mbarrier.try_wait.parity.acquire.cta.shared::cta.b64 p, [%1], %2;\n\t" \
        "selp.b32 %0, 1, 0, p;\n\t" \
        "}" \
        : "=r"(_done) : "r"(_mbar), "r"(_parity) : "memory"); \
    if (!_done) { \
        asm volatile( \
            "{\n\t" \
            ".reg .pred P1;\n\t" \
            "WAIT_LOOP_%=:\n\t" \
            "mbarrier.try_wait.parity.acquire.cta.shared::cta.b64 P1, [%0], %1, 0x989680;\n\t" \
            "@P1 bra.uni WAIT_DONE_%=;\n\t" \
            "bra.uni WAIT_LOOP_%=;\n\t" \
            "WAIT_DONE_%=:\n\t" \
            "}" \
            :: "r"(_mbar), "r"(_parity) : "memory"); \
    } \
} while(0)

#define TC_LD_X32(r, tmem_addr) \
    asm volatile( \
        "tcgen05.ld.sync.aligned.32x32b.x32.b32 " \
        "{%0, %1, %2, %3, %4, %5, %6, %7, " \
        " %8, %9, %10, %11, %12, %13, %14, %15, " \
        " %16, %17, %18, %19, %20, %21, %22, %23, " \
        " %24, %25, %26, %27, %28, %29, %30, %31}, [%32];" \
        : "=r"((r)[0]),  "=r"((r)[1]),  "=r"((r)[2]),  "=r"((r)[3]), \
          "=r"((r)[4]),  "=r"((r)[5]),  "=r"((r)[6]),  "=r"((r)[7]), \
          "=r"((r)[8]),  "=r"((r)[9]),  "=r"((r)[10]), "=r"((r)[11]), \
          "=r"((r)[12]), "=r"((r)[13]), "=r"((r)[14]), "=r"((r)[15]), \
          "=r"((r)[16]), "=r"((r)[17]), "=r"((r)[18]), "=r"((r)[19]), \
          "=r"((r)[20]), "=r"((r)[21]), "=r"((r)[22]), "=r"((r)[23]), \
          "=r"((r)[24]), "=r"((r)[25]), "=r"((r)[26]), "=r"((r)[27]), \
          "=r"((r)[28]), "=r"((r)[29]), "=r"((r)[30]), "=r"((r)[31]) \
        : "r"(tmem_addr))

#if TC_PATH
__device__ __forceinline__ void mma_tf32_ss(uint32_t d_tmem, uint64_t a_desc,
                                            uint64_t b_desc, uint32_t idesc, bool accum) {
    uint32_t en = accum ? 1u : 0u;
    asm volatile(
        "{\n\t"
        ".reg .pred p;\n\t"
        "setp.ne.u32 p, %4, 0;\n\t"
        "tcgen05.mma.cta_group::1.kind::tf32 [%0], %1, %2, %3, p;\n\t"
        "}"
        :: "r"(d_tmem), "l"(a_desc), "l"(b_desc), "r"(idesc), "r"(en)
        : "memory");
}
#endif

__device__ __forceinline__ uint64_t make_desc(uint32_t addr) {
    return ((uint64_t)2 << 61) | ((uint64_t)1 << 46) | ((uint64_t)64 << 32)
         | ((uint64_t)1 << 16) | (uint64_t)((addr >> 4) & 0x3FFF);
}

__device__ __forceinline__ uint32_t swz128(uint32_t off) {
    return off ^ ((off >> 3) & 0x70);
}

__device__ __forceinline__ void split_tf32(float v, float& hi, float& lo) {
    uint32_t h;
    asm("cvt.rna.tf32.f32 %0, %1;" : "=r"(h) : "f"(v));
    hi = __uint_as_float(h);
    lo = v - hi;
}

#define TF32_IDESC ((1u << 4) | (2u << 7) | (2u << 10) | (16u << 17) | (8u << 24))

// ---------------- fused prep kernel ----------------
#define PREP_S0 (BATCH*NFEAT*TLEN*SCL)
#define PREP_S1 (PREP_S0 + HID*K1)
#define PREP_S2 (PREP_S1 + HID*K2)
#define PREP_S3 (PREP_S2 + 3*HID*HID)
#define PREP_S4 (PREP_S3 + HID*HID)
__global__ void prep_kernel(const float* __restrict__ x,
                            const float* __restrict__ c1w, const float* __restrict__ c2w,
                            const float* __restrict__ wq, const float* __restrict__ wk,
                            const float* __restrict__ wv, const float* __restrict__ wo,
                            float* __restrict__ xcl, float* __restrict__ B1,
                            float* __restrict__ B2, float* __restrict__ wqkvT,
                            float* __restrict__ woT) {
    int idx = blockIdx.x * blockDim.x + threadIdx.x;
    if (idx < PREP_S0) {
        int w = idx % SCL;
        int h = (idx / SCL) % TLEN;
        int c = (idx / (SCL * TLEN)) % NFEAT;
        int b = idx / (SCL * TLEN * NFEAT);
        xcl[((b * TLEN + h) * SCL + w) * NFEAT + c] = x[idx];
    } else if (idx < PREP_S1) {
        int i = idx - PREP_S0;
        int n = i / K1, k = i % K1;
        int ic = k / 16, s = k % 16;
        B1[n * K1 + s * NFEAT + ic] = c1w[i];
    } else if (idx < PREP_S2) {
        int i = idx - PREP_S1;
        int n = i / K2, k = i % K2;
        int ic = k / 16, s = k % 16;
        B2[n * K2 + s * HID + ic] = c2w[i];
    } else if (idx < PREP_S3) {
        int i = idx - PREP_S2;
        int mat = i / (HID * HID);
        int r = i % (HID * HID);
        int a = r / HID, b = r % HID;
        const float* w = (mat == 0) ? wq : (mat == 1) ? wk : wv;
        wqkvT[mat * HID * HID + b * HID + a] = w[r];
    } else if (idx < PREP_S4) {
        int i = idx - PREP_S3;
        int a = i / HID, b = i % HID;
        woT[b * HID + a] = wo[i];
    }
}

// ---------------- tcgen05 3xTF32 GEMM (R8 config + optional split-K) ----------------
// MODE 0: A row-major. MODE 1: conv1 im2col. MODE 2: conv2 im2col.
// MODE 3: A gathered from (upd|vmean) via sel map.
// SPLITK > 1: grid.z splits K; raw partial written to o0 + z*M*HID (no bias/relu).
#define GEMM_SMEM_BYTES (79872)

template<int MODE, int KDIM, bool RELU, int NMAT, int LAYOUT, int SPLITK>
__global__ void __launch_bounds__(256, 2)
gemm_tc_kernel(const float* __restrict__ Ain, const float* __restrict__ BwAll,
               const float* __restrict__ b0, const float* __restrict__ b1p,
               const float* __restrict__ b2p,
               float* __restrict__ o0, float* __restrict__ o1p, float* __restrict__ o2p,
               int M,
               const int* __restrict__ sel, const float* __restrict__ updp,
               const float* __restrict__ vmeanp) {
    const int mat = (NMAT > 1) ? blockIdx.y : 0;
    const float* Bw = BwAll + (size_t)mat * HID * KDIM;
    const float* bias = (mat == 0) ? b0 : (mat == 1) ? b1p : b2p;
    float* out = (mat == 0) ? o0 : (mat == 1) ? o1p : o2p;
    const int kbeg = (SPLITK > 1) ? blockIdx.z * (KDIM / SPLITK) : 0;

#if TC_PATH
    extern __shared__ char dynraw[];
    __shared__ uint32_t s_tmem[1];
    __shared__ __align__(8) unsigned long long s_mbar[1];

    const int tid = threadIdx.x;
    const int wid = tid >> 5;
    const int lane = tid & 31;
    const int block_m = blockIdx.x * 128;

    uint32_t dynb32 = smem_u32(dynraw);
    uint32_t smem_base = (dynb32 + 1023u) & ~1023u;
    char* dbase = dynraw + (smem_base - dynb32);
    uint32_t mbar0 = smem_u32(&s_mbar[0]);

    if (wid == 0) {
        TC_ALLOC(smem_u32(s_tmem), 256);
        TC_RELINQ();
    }
    if (tid == 0) MB_INIT(mbar0, 1);
    __syncthreads();
    uint32_t tmem;
    asm volatile("ld.shared.b32 %0, [%1];" : "=r"(tmem) : "r"(smem_u32(s_tmem)));

    const int quad = tid & 7;
    int rowi[4], abase[4], bh2[4];
    bool aok[4];
#pragma unroll
    for (int i = 0; i < 4; i++) {
        rowi[i] = i * 32 + (tid >> 3);
        int m = block_m + rowi[i];
        aok[i] = (m < M);
        int mc = aok[i] ? m : 0;
        bh2[i] = 0;
        if (MODE == 0) {
            abase[i] = mc * KDIM;
        } else if (MODE == 1) {
            int b = mc / (H1H * H1W);
            int r = mc % (H1H * H1W);
            abase[i] = ((b * TLEN + r / H1W) * SCL + (r % H1W)) * NFEAT;
        } else if (MODE == 2) {
            int b = mc / LSEQ;
            int r = mc % LSEQ;
            abase[i] = ((b * H1H + r / H2W) * H1W + (r % H2W)) * HID;
        } else {
            int b = mc / LSEQ;
            int l = mc % LSEQ;
            abase[i] = b * NHEAD * LSEQ + l;
            bh2[i] = b * NHEAD;
        }
    }
    uint32_t swz[4];
#pragma unroll
    for (int i = 0; i < 4; i++)
        swz[i] = swz128((uint32_t)rowi[i] * 128u + (uint32_t)quad * 16u);

    float4 areg[4], breg[4];
    auto load_regs = [&](int c) {
        const int kq = kbeg + c * 32 + quad * 4;
#pragma unroll
        for (int i = 0; i < 4; i++) {
            areg[i] = make_float4(0.f, 0.f, 0.f, 0.f);
            if (aok[i]) {
                if (MODE == 3) {
                    int h = kq >> 6, d = kq & 63;
                    int u = __ldg(&sel[abase[i] + h * LSEQ]);
                    int bh = bh2[i] + h;
                    const float* src = (u >= 0)
                        ? updp + ((size_t)bh * UTOP + u) * DHEAD + d
                        : vmeanp + bh * DHEAD + d;
                    areg[i] = *reinterpret_cast<const float4*>(src);
                } else {
                    int addr;
                    if (MODE == 0) {
                        addr = abase[i] + kq;
                    } else if (MODE == 1) {
                        int s = kq >> 4, ic = kq & 15;
                        addr = abase[i] + (((s >> 2) * SCL) + (s & 3)) * NFEAT + ic;
                    } else {
                        int s = kq >> 7, ic = kq & 127;
                        addr = abase[i] + (((s >> 2) * H1W) + (s & 3)) * HID + ic;
                    }
                    areg[i] = *reinterpret_cast<const float4*>(Ain + addr);
                }
            }
            breg[i] = *reinterpret_cast<const float4*>(Bw + rowi[i] * KDIM + kq);
        }
    };
    auto store_tiles = [&]() {
        char* Ahi = dbase;
        char* Alo = Ahi + 16384;
        char* Bhi = Ahi + 32768;
        char* Blo = Ahi + 49152;
#pragma unroll
        for (int i = 0; i < 4; i++) {
            float4 h4, l4;
            split_tf32(areg[i].x, h4.x, l4.x);
            split_tf32(areg[i].y, h4.y, l4.y);
            split_tf32(areg[i].z, h4.z, l4.z);
            split_tf32(areg[i].w, h4.w, l4.w);
            *reinterpret_cast<float4*>(Ahi + swz[i]) = h4;
            *reinterpret_cast<float4*>(Alo + swz[i]) = l4;
            split_tf32(breg[i].x, h4.x, l4.x);
            split_tf32(breg[i].y, h4.y, l4.y);
            split_tf32(breg[i].z, h4.z, l4.z);
            split_tf32(breg[i].w, h4.w, l4.w);
            *reinterpret_cast<float4*>(Bhi + swz[i]) = h4;
            *reinterpret_cast<float4*>(Blo + swz[i]) = l4;
        }
    };

    const int NC = (KDIM / SPLITK) / 32;
    int ph = 0;
    load_regs(0);

    for (int c = 0; c < NC; c++) {
        if (c > 0) {
            MB_WAIT_PARITY(mbar0, ph);
            ph ^= 1;
        }
        store_tiles();
        if (c + 1 < NC) load_regs(c + 1);
        FENCE_ASYNC();
        __syncthreads();
        if (tid == 0) {
            uint64_t dah = make_desc(smem_base);
            uint64_t dal = make_desc(smem_base + 16384);
            uint64_t dbh = make_desc(smem_base + 32768);
            uint64_t dbl = make_desc(smem_base + 49152);
#pragma unroll
            for (int s = 0; s < 4; s++) {
                uint64_t o = (uint64_t)(s * 2);
                mma_tf32_ss(tmem, dah + o, dbh + o, TF32_IDESC, !(c == 0 && s == 0));
                mma_tf32_ss(tmem, dah + o, dbl + o, TF32_IDESC, true);
                mma_tf32_ss(tmem, dal + o, dbh + o, TF32_IDESC, true);
            }
            TC_COMMIT(mbar0);
        }
    }
    MB_WAIT_PARITY(mbar0, ph);
    TC_FENCE_AFTER();
    __syncthreads();

    if (wid < 4) {
        int m = block_m + wid * 32 + lane;
#pragma unroll
        for (int cb = 0; cb < 128; cb += 32) {
            uint32_t r[32];
            TC_LD_X32(r, tmem + cb);
            TC_WAIT_LD();
            if (m < M) {
                float vals[32];
#pragma unroll
                for (int j = 0; j < 32; j++) {
                    float v = __uint_as_float(r[j]);
                    if (SPLITK == 1) {
                        v += __ldg(&bias[cb + j]);
                        if (RELU) v = fmaxf(v, 0.f);
                    }
                    vals[j] = v;
                }
                float* po;
                if (SPLITK > 1) {
                    po = o0 + ((size_t)blockIdx.z * M + m) * HID + cb;
                } else if (LAYOUT == 0) {
                    po = out + (size_t)m * HID + cb;
                } else {
                    int b = m / LSEQ, l = m % LSEQ;
                    int h = cb >> 6, d0 = cb & 63;
                    po = out + ((size_t)(b * NHEAD + h) * LSEQ + l) * DHEAD + d0;
                }
#pragma unroll
                for (int j = 0; j < 8; j++) {
                    *reinterpret_cast<float4*>(po + j * 4) =
                        make_float4(vals[j * 4], vals[j * 4 + 1], vals[j * 4 + 2], vals[j * 4 + 3]);
                }
            }
        }
        TC_FENCE_BEFORE();
    }
    __syncthreads();
    if (wid == 0) TC_DEALLOC(tmem, 256);
#else
    // naive fallback (family PTX pass; exact sm_103a cubin preferred on GB300)
    const int tid = threadIdx.x;
    const int block_m = blockIdx.x * 128;
    const int kdiv = KDIM / SPLITK;
    for (int e = tid; e < 128 * 128; e += 256) {
        int mi = e >> 7, n = e & 127;
        int m = block_m + mi;
        if (m >= M) continue;
        float acc = 0.f;
        for (int kk = 0; kk < kdiv; kk++) {
            int k = kbeg + kk;
            float a;
            if (MODE == 0) {
                a = Ain[(size_t)m * KDIM + k];
            } else if (MODE == 1) {
                int b = m / (H1H * H1W), r = m % (H1H * H1W);
                int s = k >> 4, ic = k & 15;
                a = Ain[((b * TLEN + r / H1W + (s >> 2)) * SCL + (r % H1W) + (s & 3)) * NFEAT + ic];
            } else if (MODE == 2) {
                int b = m / LSEQ, r = m % LSEQ;
                int s = k >> 7, ic = k & 127;
                a = Ain[((b * H1H + r / H2W + (s >> 2)) * H1W + (r % H2W) + (s & 3)) * HID + ic];
            } else {
                int b = m / LSEQ, l = m % LSEQ;
                int h = k >> 6, d = k & 63;
                int u = sel[(b * NHEAD + h) * LSEQ + l];
                int bh = b * NHEAD + h;
                a = (u >= 0) ? updp[((size_t)bh * UTOP + u) * DHEAD + d]
                             : vmeanp[bh * DHEAD + d];
            }
            acc += a * Bw[n * KDIM + k];
        }
        if (SPLITK > 1) {
            o0[((size_t)blockIdx.z * M + m) * HID + n] = acc;
        } else {
            acc += bias[n];
            if (RELU) acc = fmaxf(acc, 0.f);
            if (LAYOUT == 0) {
                out[(size_t)m * HID + n] = acc;
            } else {
                int b = m / LSEQ, l = m % LSEQ;
                int h = n >> 6, d = n & 63;
                out[((size_t)(b * NHEAD + h) * LSEQ + l) * DHEAD + d] = acc;
            }
        }
    }
#endif
}

// ---------------- split-K reduce (+bias+relu) ----------------
__global__ void reduce2_kernel(const float* __restrict__ part, const float* __restrict__ bias,
                               float* __restrict__ out) {
    int idx = blockIdx.x * blockDim.x + threadIdx.x;   // float4 units
    if (idx >= M2 * HID / 4) return;
    float4 a = *reinterpret_cast<const float4*>(part + (size_t)idx * 4);
    float4 b = *reinterpret_cast<const float4*>(part + (size_t)M2 * HID + (size_t)idx * 4);
    int n = (idx * 4) & 127;
    float4 r;
    r.x = fmaxf(a.x + b.x + bias[n], 0.f);
    r.y = fmaxf(a.y + b.y + bias[n + 1], 0.f);
    r.z = fmaxf(a.z + b.z + bias[n + 2], 0.f);
    r.w = fmaxf(a.w + b.w + bias[n + 3], 0.f);
    *reinterpret_cast<float4*>(out + (size_t)idx * 4) = r;
}

// ---------------- helpers ----------------
__device__ __forceinline__ float warp_sum(float v) {
    v += __shfl_xor_sync(0xffffffffu, v, 16);
    v += __shfl_xor_sync(0xffffffffu, v, 8);
    v += __shfl_xor_sync(0xffffffffu, v, 4);
    v += __shfl_xor_sync(0xffffffffu, v, 2);
    v += __shfl_xor_sync(0xffffffffu, v, 1);
    return v;
}
__device__ __forceinline__ float warp_max(float v) {
    v = fmaxf(v, __shfl_xor_sync(0xffffffffu, v, 16));
    v = fmaxf(v, __shfl_xor_sync(0xffffffffu, v, 8));
    v = fmaxf(v, __shfl_xor_sync(0xffffffffu, v, 4));
    v = fmaxf(v, __shfl_xor_sync(0xffffffffu, v, 2));
    v = fmaxf(v, __shfl_xor_sync(0xffffffffu, v, 1));
    return v;
}

// ---------------- sampled scores -> M ----------------
__global__ void sampled_m_kernel(const float* __restrict__ Q, const float* __restrict__ K,
                                 const int* __restrict__ idxs, float* __restrict__ Mout) {
    int gwarp = (blockIdx.x * blockDim.x + threadIdx.x) >> 5;
    int lane = threadIdx.x & 31;
    if (gwarp >= BHCNT * LSEQ) return;
    int bh = gwarp / LSEQ;
    int l  = gwarp % LSEQ;
    const float* q = Q + (size_t)gwarp * DHEAD;
    float q0 = q[lane * 2], q1 = q[lane * 2 + 1];
    const float* Kb = K + (size_t)bh * LSEQ * DHEAD;
    float mx = NEG_INF, sm = 0.f;
#pragma unroll 1
    for (int u = 0; u < UTOP; u += 8) {
        float d[8];
#pragma unroll
        for (int j = 0; j < 8; j++) {
            int ki = __ldg(&idxs[l * UTOP + u + j]);
            const float* kr = Kb + (size_t)ki * DHEAD;
            d[j] = q0 * kr[lane * 2] + q1 * kr[lane * 2 + 1];
        }
#pragma unroll
        for (int j = 0; j < 8; j++) d[j] = warp_sum(d[j]);
#pragma unroll
        for (int j = 0; j < 8; j++) { mx = fmaxf(mx, d[j]); sm += d[j]; }
    }
    if (lane == 0) Mout[gwarp] = mx - sm / (float)LSEQ;
}

// ---------------- top-40 via bitonic sort of 2048 keys ----------------
#define SORTN 2048
__global__ void __launch_bounds__(256)
topk_kernel(const float* __restrict__ Min, int* __restrict__ Mtop) {
    __shared__ unsigned long long keys[SORTN];
    int bh = blockIdx.x;
    int tid = threadIdx.x;
    for (int j = tid; j < SORTN; j += 256) {
        unsigned long long key;
        if (j < LSEQ) {
            uint32_t b = __float_as_uint(Min[bh * LSEQ + j]);
            uint32_t s = (b & 0x80000000u) ? ~b : (b | 0x80000000u);
            key = ((unsigned long long)(~s) << 32) | (uint32_t)j;
        } else {
            key = 0xFFFFFFFFFFFFFFFFull;
        }
        keys[j] = key;
    }
    __syncthreads();
    for (int k = 2; k <= SORTN; k <<= 1) {
        for (int j = k >> 1; j > 0; j >>= 1) {
#pragma unroll 4
            for (int t = tid; t < SORTN / 2; t += 256) {
                int i = ((t / j) * j * 2) + (t % j);
                int l2 = i + j;
                bool up = ((i & k) == 0);
                unsigned long long a = keys[i], b = keys[l2];
                if ((a > b) == up) { keys[i] = b; keys[l2] = a; }
            }
            __syncthreads();
        }
    }
    if (tid < UTOP)
        Mtop[bh * UTOP + tid] = (int)(keys[tid] & 0xFFFFFFFFull);
}

// ---------------- V mean per (b,h) ----------------
#define VSLICE 377
__global__ void vmean_kernel(const float* __restrict__ V, float* __restrict__ vmean) {
    __shared__ float part[4][DHEAD];
    int bh = blockIdx.x;
    int tid = threadIdx.x;
    int d = tid & 63;
    int sl = tid >> 6;
    const float* Vb = V + (size_t)bh * LSEQ * DHEAD;
    float s = 0.f;
    int beg = sl * VSLICE, end = beg + VSLICE;
    for (int l = beg; l < end; l++) s += Vb[(size_t)l * DHEAD + d];
    part[sl][d] = s;
    __syncthreads();
    if (tid < DHEAD)
        vmean[bh * DHEAD + tid] =
            (part[0][tid] + part[1][tid] + part[2][tid] + part[3][tid]) / (float)LSEQ;
}

// ---------------- attention: tiled multi-query (8 queries/block, K/V smem) ------
// grid = BHCNT * 5 blocks (each handles 8 of the 40 selected queries),
// 256 threads = 8 warps, 1 warp per query. Per 32-key chunk:
// phase A: lane=key, scalar-LDS dot (Ks padded 65 -> conflict-free, no shuffles);
// phase B: lane=dim pair, p broadcast from smem.
#define AQ 8
#define NCHUNK ((LSEQ + 31) / 32)   // 48
__global__ void __launch_bounds__(256)
attn_kernel(const float* __restrict__ Q, const float* __restrict__ K,
            const float* __restrict__ V, const int* __restrict__ Mtop,
            float* __restrict__ upd) {
    __shared__ float qs[AQ][DHEAD];
    __shared__ float Ks[32][65];
    __shared__ float2 Vs[32][33];
    __shared__ float ps[AQ][32];
    int bh = blockIdx.x / 5;
    int grp = blockIdx.x % 5;
    int tid = threadIdx.x;
    int w = tid >> 5;
    int lane = tid & 31;
    int u = grp * AQ + w;
    int qi = bh * UTOP + u;
    int l = Mtop[qi];

    // load 8 query rows
    for (int e = tid; e < AQ * DHEAD; e += 256) {
        int uu = e >> 6, d = e & 63;
        int ll = Mtop[bh * UTOP + grp * AQ + uu];
        qs[uu][d] = Q[((size_t)bh * LSEQ + ll) * DHEAD + d];
    }
    __syncthreads();
    (void)l;

    const float* Kb = K + (size_t)bh * LSEQ * DHEAD;
    const float* Vb = V + (size_t)bh * LSEQ * DHEAD;

    float m = NEG_INF, s = 0.f, acc0 = 0.f, acc1 = 0.f;

    for (int c = 0; c < NCHUNK; c++) {
        int base = c * 32;
        int nk = LSEQ - base; if (nk > 32) nk = 32;
        // cooperative tile load
        for (int e = tid; e < nk * DHEAD; e += 256) {
            int row = e >> 6, d = e & 63;
            float kv = Kb[(size_t)(base + row) * DHEAD + d];
            Ks[row][d] = kv;
            if ((d & 1) == 0) {
                // load V as float2 pairs: handled below separately
            }
        }
        for (int e = tid; e < nk * 32; e += 256) {
            int row = e >> 5, dp = e & 31;
            Vs[row][dp] = *reinterpret_cast<const float2*>(
                Vb + (size_t)(base + row) * DHEAD + dp * 2);
        }
        __syncthreads();

        // phase A: lane = key
        bool valid = (lane < nk);
        float dot = 0.f;
#pragma unroll 16
        for (int d = 0; d < DHEAD; d++)
            dot += Ks[lane][d] * qs[w][d];
        dot *= 0.125f;
        if (!valid) dot = NEG_INF;
        float cm = warp_max(dot);
        float nm = fmaxf(m, cm);
        float scale = __expf(m - nm);
        float p = valid ? __expf(dot - nm) : 0.f;
        ps[w][lane] = p;
        float cs = warp_sum(p);
        s = s * scale + cs;
        acc0 *= scale;
        acc1 *= scale;
        m = nm;
        __syncwarp();
        // phase B: lane = dim pair
#pragma unroll 8
        for (int k = 0; k < 32; k++) {
            float pk = ps[w][k];
            float2 vv = Vs[k][lane];
            acc0 += pk * vv.x;
            acc1 += pk * vv.y;
        }
        __syncthreads();
    }
    float inv = 1.f / s;
    upd[(size_t)qi * DHEAD + lane * 2]     = acc0 * inv;
    upd[(size_t)qi * DHEAD + lane * 2 + 1] = acc1 * inv;
}

// ---------------- sel map ----------------
__global__ void selinit_kernel(int* __restrict__ sel) {
    int idx = blockIdx.x * blockDim.x + threadIdx.x;
    if (idx < BHCNT * LSEQ) sel[idx] = -1;
}
__global__ void selset_kernel(const int* __restrict__ Mtop, int* __restrict__ sel) {
    int idx = blockIdx.x * blockDim.x + threadIdx.x;
    if (idx >= BHCNT * UTOP) return;
    sel[(idx / UTOP) * LSEQ + Mtop[idx]] = idx % UTOP;
}

// ---------------- launch ----------------
extern "C" void kernel_launch(void* const* d_in, const int* in_sizes, int n_in,
                              void* d_out, int out_size) {
    const float* x       = (const float*)d_in[0];
    const float* conv1_w = (const float*)d_in[1];
    const float* conv1_b = (const float*)d_in[2];
    const float* conv2_w = (const float*)d_in[3];
    const float* conv2_b = (const float*)d_in[4];
    const float* wq = (const float*)d_in[5];
    const float* bq = (const float*)d_in[6];
    const float* wk = (const float*)d_in[7];
    const float* bk = (const float*)d_in[8];
    const float* wv = (const float*)d_in[9];
    const float* bv = (const float*)d_in[10];
    const float* wo = (const float*)d_in[11];
    const float* bo = (const float*)d_in[12];
    const int* index_sample = (const int*)d_in[13];
    float* out = (float*)d_out;

    float *xcl, *h1cl, *seq, *part, *Qp, *Kp, *Vp, *Mv, *updv, *vmeanv;
    float *B1, *B2, *wqkvT, *woT;
    int *mtop, *sel;
    cudaGetSymbolAddress((void**)&xcl, g_xcl);
    cudaGetSymbolAddress((void**)&h1cl, g_h1cl);
    cudaGetSymbolAddress((void**)&seq, g_seq);
    cudaGetSymbolAddress((void**)&part, g_part);
    cudaGetSymbolAddress((void**)&Qp, g_Q);
    cudaGetSymbolAddress((void**)&Kp, g_K);
    cudaGetSymbolAddress((void**)&Vp, g_V);
    cudaGetSymbolAddress((void**)&Mv, g_M);
    cudaGetSymbolAddress((void**)&mtop, g_Mtop);
    cudaGetSymbolAddress((void**)&updv, g_upd);
    cudaGetSymbolAddress((void**)&vmeanv, g_vmean);
    cudaGetSymbolAddress((void**)&B1, g_B1);
    cudaGetSymbolAddress((void**)&B2, g_B2);
    cudaGetSymbolAddress((void**)&wqkvT, g_wqkvT);
    cudaGetSymbolAddress((void**)&woT, g_woT);
    cudaGetSymbolAddress((void**)&sel, g_sel);

    cudaFuncSetAttribute((const void*)gemm_tc_kernel<1, K1, true, 1, 0, 1>,
                         cudaFuncAttributeMaxDynamicSharedMemorySize, GEMM_SMEM_BYTES);
    cudaFuncSetAttribute((const void*)gemm_tc_kernel<2, K2, false, 1, 0, 2>,
                         cudaFuncAttributeMaxDynamicSharedMemorySize, GEMM_SMEM_BYTES);
    cudaFuncSetAttribute((const void*)gemm_tc_kernel<0, HID, false, 3, 1, 1>,
                         cudaFuncAttributeMaxDynamicSharedMemorySize, GEMM_SMEM_BYTES);
    cudaFuncSetAttribute((const void*)gemm_tc_kernel<3, HID, false, 1, 0, 1>,
                         cudaFuncAttributeMaxDynamicSharedMemorySize, GEMM_SMEM_BYTES);

    // fused prep
    prep_kernel<<<(PREP_S4 + 255) / 256, 256>>>(x, conv1_w, conv2_w, wq, wk, wv, wo,
                                                xcl, B1, B2, wqkvT, woT);

    // conv1 -> h1cl (NHWC row-major), relu
    gemm_tc_kernel<1, K1, true, 1, 0, 1>
        <<<(M1 + 127) / 128, 256, GEMM_SMEM_BYTES>>>(xcl, B1, conv1_b, conv1_b, conv1_b,
                                                     h1cl, h1cl, h1cl, M1,
                                                     nullptr, nullptr, nullptr);

    // conv2 split-K=2 -> partials -> reduce(+bias+relu) -> seq
    gemm_tc_kernel<2, K2, false, 1, 0, 2>
        <<<dim3((M2 + 127) / 128, 1, 2), 256, GEMM_SMEM_BYTES>>>(
            h1cl, B2, conv2_b, conv2_b, conv2_b, part, part, part, M2,
            nullptr, nullptr, nullptr);
    reduce2_kernel<<<(M2 * HID / 4 + 255) / 256, 256>>>(part, conv2_b, seq);

    // QKV: grid.y = 3, head layout
    gemm_tc_kernel<0, HID, false, 3, 1, 1>
        <<<dim3((M2 + 127) / 128, 3), 256, GEMM_SMEM_BYTES>>>(seq, wqkvT, bq, bk, bv,
                                                              Qp, Kp, Vp, M2,
                                                              nullptr, nullptr, nullptr);

    // sampled scores -> M
    {
        int warps = BHCNT * LSEQ;
        sampled_m_kernel<<<(warps + 7) / 8, 256>>>(Qp, Kp, index_sample, Mv);
    }

    // top-40 (bitonic) + vmean
    topk_kernel<<<BHCNT, 256>>>(Mv, mtop);
    vmean_kernel<<<BHCNT, 256>>>(Vp, vmeanv);

    // sel map
    selinit_kernel<<<(BHCNT * LSEQ + 255) / 256, 256>>>(sel);
    selset_kernel<<<(BHCNT * UTOP + 255) / 256, 256>>>(mtop, sel);

    // attention (tiled multi-query)
    attn_kernel<<<BHCNT * 5, 256>>>(Qp, Kp, Vp, mtop, updv);

    // final projection with fused ctx gather (MODE 3)
    gemm_tc_kernel<3, HID, false, 1, 0, 1>
        <<<(M2 + 127) / 128, 256, GEMM_SMEM_BYTES>>>(nullptr, woT, bo, bo, bo,
                                                     out, out, out, M2,
                                                     sel, updv, vmeanv);
}